// round 1
// baseline (speedup 1.0000x reference)
#include <cuda_runtime.h>
#include <math.h>
#include <stdint.h>

#define CS    8
#define KC    256
#define NH    16
#define D     64
#define CDIM  1024
#define MAXB  8
#define MAXLK 4096
#define MAXTOK (MAXB*MAXLK)

// ---------------- device scratch (no allocations allowed) ----------------
__device__ int   g_idx[MAXTOK];
__device__ int   g_counts[MAXB*KC];
__device__ int   g_offsets[MAXB*KC];
__device__ int   g_cursor[MAXB*KC];
__device__ int   g_perm[MAXTOK];
__device__ float g_codv[MAXB*KC*CDIM];   // 8 MB
__device__ float g_codk[KC*CDIM];        // 1 MB

// ---------------- K0: zero counts ----------------
__global__ void zero_counts_kernel(int n) {
    int i = blockIdx.x * blockDim.x + threadIdx.x;
    if (i < n) g_counts[i] = 0;
}

// ---------------- K1: bucket index per kv token + histogram ----------------
// block = 256 threads = 8 warps, each warp processes 8 rows
__global__ void __launch_bounds__(256) idx_kernel(
    const float* __restrict__ k, const float* __restrict__ Wc,
    const float* __restrict__ bc, int Lk, int nTok)
{
    __shared__ float4 sW[CS * (CDIM/4)];   // 32 KB
    __shared__ float  sbc[CS];
    int t = threadIdx.x;
    for (int i = t; i < CS * (CDIM/4); i += 256) sW[i] = ((const float4*)Wc)[i];
    if (t < CS) sbc[t] = bc[t];
    __syncthreads();

    int warp = t >> 5, lane = t & 31;
    int rowBase = (blockIdx.x * 8 + warp) * 8;
    for (int rr = 0; rr < 8; rr++) {
        int r = rowBase + rr;
        if (r >= nTok) return;
        const float4* krow = (const float4*)(k + (size_t)r * CDIM);
        float acc[CS];
        #pragma unroll
        for (int j = 0; j < CS; j++) acc[j] = 0.f;
        for (int i = lane; i < CDIM/4; i += 32) {
            float4 kv = krow[i];
            #pragma unroll
            for (int j = 0; j < CS; j++) {
                float4 w = sW[j * (CDIM/4) + i];
                acc[j] += kv.x*w.x + kv.y*w.y + kv.z*w.z + kv.w*w.w;
            }
        }
        #pragma unroll
        for (int j = 0; j < CS; j++) {
            #pragma unroll
            for (int o = 16; o >= 1; o >>= 1)
                acc[j] += __shfl_xor_sync(0xffffffffu, acc[j], o);
        }
        if (lane == 0) {
            int code = 0;
            #pragma unroll
            for (int j = 0; j < CS; j++)
                if (acc[j] + sbc[j] >= 0.f) code |= (1 << (7 - j));
            g_idx[r] = code;
            int b = r / Lk;
            atomicAdd(&g_counts[b * KC + code], 1);
        }
    }
}

// ---------------- K2: per-batch exclusive scan -> offsets, cursor ----------------
__global__ void scan_kernel(int B, int Lk) {
    __shared__ int s[KC];
    int t = threadIdx.x;  // 256
    for (int b = 0; b < B; b++) {
        int v = g_counts[b * KC + t];
        s[t] = v;
        __syncthreads();
        for (int o = 1; o < KC; o <<= 1) {
            int x = (t >= o) ? s[t - o] : 0;
            __syncthreads();
            s[t] += x;
            __syncthreads();
        }
        int off = b * Lk + (s[t] - v);
        g_offsets[b * KC + t] = off;
        g_cursor[b * KC + t]  = off;
        __syncthreads();
    }
}

// ---------------- K3: scatter token ids into bucket lists ----------------
__global__ void scatter_kernel(int Lk, int nTok) {
    int r = blockIdx.x * blockDim.x + threadIdx.x;
    if (r >= nTok) return;
    int b = r / Lk;
    int code = g_idx[r];
    int pos = atomicAdd(&g_cursor[b * KC + code], 1);
    g_perm[pos] = r;
}

// ---------------- K4: dense codebook keys cod_k[K][C] ----------------
__global__ void codk_kernel(const float* __restrict__ cb) {
    int c = blockIdx.x, t = threadIdx.x;   // 256 threads, one float4 each
    float4 acc = make_float4(0.f, 0.f, 0.f, 0.f);
    #pragma unroll
    for (int j = 0; j < CS; j++) {
        int sel = ((c >> (7 - j)) & 1) ? j : (CS + j);
        float4 w = ((const float4*)cb)[sel * (CDIM/4) + t];
        acc.x += w.x; acc.y += w.y; acc.z += w.z; acc.w += w.w;
    }
    ((float4*)g_codv)[0]; // no-op (keep compiler honest about symbol usage)
    ((float4*)g_codk)[c * (CDIM/4) + t] = acc;
}

// ---------------- K5: gather-sum v rows per bucket (deterministic order) ----------------
__global__ void __launch_bounds__(256) gather_kernel(const float* __restrict__ v) {
    int bk = blockIdx.x;              // b*KC + bucket
    int t0 = g_offsets[bk];
    int cnt = g_counts[bk];
    __shared__ int toks[1024];
    int t = threadIdx.x;
    int n = min(cnt, 1024);
    for (int i = t; i < n; i += 256) toks[i] = g_perm[t0 + i];
    __syncthreads();
    if (t == 0 && n > 1) {            // insertion sort (avg bucket ~16 tokens)
        for (int i = 1; i < n; i++) {
            int key = toks[i]; int j = i - 1;
            while (j >= 0 && toks[j] > key) { toks[j + 1] = toks[j]; j--; }
            toks[j + 1] = key;
        }
    }
    __syncthreads();
    float4 acc = make_float4(0.f, 0.f, 0.f, 0.f);
    for (int i = 0; i < cnt; i++) {
        int row = (i < n) ? toks[i] : g_perm[t0 + i];
        float4 x = *(const float4*)(v + (size_t)row * CDIM + t * 4);
        acc.x += x.x; acc.y += x.y; acc.z += x.z; acc.w += x.w;
    }
    *(float4*)(g_codv + (size_t)bk * CDIM + t * 4) = acc;
}

// ---------------- K6: bucketed attention ----------------
// grid (Lq/64, H, B), 256 threads, ~157KB dynamic smem.
// smem float layout:
//   Qs  [64][64]    4096   (reused as swizzled output accumulator Os)
//   KP  [256][68]  17408   (Ks during scores, then P[k][r])
//   Vs  [256][68]  17408
//   cnt [256]        256
//   den [64]          64
#define SM_QS   0
#define SM_KP   4096
#define SM_VS   (4096 + 17408)
#define SM_CNT  (4096 + 17408 + 17408)
#define SM_DEN  (SM_CNT + 256)
#define SM_FLOATS (SM_DEN + 64)

__global__ void __launch_bounds__(256, 1) attn_kernel(
    const float* __restrict__ q, float* __restrict__ out, int Lq)
{
    extern __shared__ float sm[];
    float* Qs  = sm + SM_QS;
    float* KP  = sm + SM_KP;
    float* Vs  = sm + SM_VS;
    float* cntf = sm + SM_CNT;
    float* denS = sm + SM_DEN;

    const int t  = threadIdx.x;
    const int h  = blockIdx.y, b = blockIdx.z;
    const int q0 = blockIdx.x * 64;

    // ---- load tiles ----
    const float* qbase = q + ((size_t)(b * Lq + q0)) * CDIM + h * D;
    #pragma unroll
    for (int i = 0; i < 4; i++) {
        int s = t + 256 * i;
        int r = s >> 4, d4 = s & 15;
        *(float4*)(Qs + r * 64 + d4 * 4) =
            *(const float4*)(qbase + (size_t)r * CDIM + d4 * 4);
    }
    const float* kbase = g_codk + h * D;
    #pragma unroll
    for (int i = 0; i < 16; i++) {
        int s = t + 256 * i;
        int c = s >> 4, d4 = s & 15;
        *(float4*)(KP + c * 68 + d4 * 4) =
            *(const float4*)(kbase + (size_t)c * CDIM + d4 * 4);
    }
    const float* vbase = g_codv + ((size_t)b * KC) * CDIM + h * D;
    #pragma unroll
    for (int i = 0; i < 16; i++) {
        int s = t + 256 * i;
        int c = s >> 4, d4 = s & 15;
        *(float4*)(Vs + c * 68 + d4 * 4) =
            *(const float4*)(vbase + (size_t)c * CDIM + d4 * 4);
    }
    cntf[t] = (float)g_counts[b * KC + t];
    __syncthreads();

    // ---- scores: S[64][256], thread tile 4 rows x 16 buckets ----
    const int c_idx = t & 15, r_idx = t >> 4;
    float acc[4][16];
    #pragma unroll
    for (int i = 0; i < 4; i++)
        #pragma unroll
        for (int j = 0; j < 16; j++) acc[i][j] = 0.f;

    #pragma unroll 4
    for (int d0 = 0; d0 < 64; d0 += 4) {
        float4 qv[4];
        #pragma unroll
        for (int i = 0; i < 4; i++)
            qv[i] = *(float4*)(Qs + (r_idx * 4 + i) * 64 + d0);
        #pragma unroll
        for (int j = 0; j < 16; j++) {
            float4 kv = *(float4*)(KP + (c_idx + 16 * j) * 68 + d0);
            #pragma unroll
            for (int i = 0; i < 4; i++)
                acc[i][j] += qv[i].x*kv.x + qv[i].y*kv.y + qv[i].z*kv.z + qv[i].w*kv.w;
        }
    }

    // ---- masked unnormalized softmax + den (softmax sum cancels in num/den) ----
    float cnt[16];
    #pragma unroll
    for (int j = 0; j < 16; j++) cnt[j] = cntf[c_idx + 16 * j];
    const float scale = 0.125f;   // 1/sqrt(64)
    float den[4];
    #pragma unroll
    for (int i = 0; i < 4; i++) {
        float mx = -1e30f;
        #pragma unroll
        for (int j = 0; j < 16; j++) {
            float s = acc[i][j] * scale;
            acc[i][j] = s;
            if (cnt[j] > 0.f) mx = fmaxf(mx, s);
        }
        #pragma unroll
        for (int o = 8; o >= 1; o >>= 1)
            mx = fmaxf(mx, __shfl_xor_sync(0xffffffffu, mx, o));
        float dsum = 0.f;
        #pragma unroll
        for (int j = 0; j < 16; j++) {
            float p = (cnt[j] > 0.f) ? __expf(acc[i][j] - mx) : 0.f;
            acc[i][j] = p;
            dsum += p * cnt[j];
        }
        #pragma unroll
        for (int o = 8; o >= 1; o >>= 1)
            dsum += __shfl_xor_sync(0xffffffffu, dsum, o);
        den[i] = dsum;
    }
    __syncthreads();   // all Ks reads done; KP becomes P[k][r]

    #pragma unroll
    for (int j = 0; j < 16; j++)
        #pragma unroll
        for (int i = 0; i < 4; i++)
            KP[(c_idx + 16 * j) * 68 + r_idx * 4 + i] = acc[i][j];
    if (c_idx == 0) {
        #pragma unroll
        for (int i = 0; i < 4; i++) denS[r_idx * 4 + i] = den[i];
    }
    __syncthreads();

    // ---- PV: split-K, 4 groups x 64 threads, thread tile 8 rows x 8 dcols ----
    const int g  = t >> 6, tg = t & 63;
    const int tr = tg & 7, td = tg >> 3;
    float o_[8][8];
    #pragma unroll
    for (int i = 0; i < 8; i++)
        #pragma unroll
        for (int j = 0; j < 8; j++) o_[i][j] = 0.f;

    const int k0 = g * 64;
    #pragma unroll 4
    for (int kk = 0; kk < 64; kk++) {
        const float* Pr = KP + (k0 + kk) * 68 + tr * 8;
        const float* Vr = Vs + (k0 + kk) * 68 + td * 8;
        float4 p0 = *(const float4*)Pr,       p1 = *(const float4*)(Pr + 4);
        float4 v0 = *(const float4*)Vr,       v1 = *(const float4*)(Vr + 4);
        float pv[8] = {p0.x,p0.y,p0.z,p0.w,p1.x,p1.y,p1.z,p1.w};
        float vv[8] = {v0.x,v0.y,v0.z,v0.w,v1.x,v1.y,v1.z,v1.w};
        #pragma unroll
        for (int i = 0; i < 8; i++)
            #pragma unroll
            for (int j = 0; j < 8; j++)
                o_[i][j] += pv[i] * vv[j];
    }

    // ---- staged cross-group reduce into Os (=Qs), XOR-swizzled float4 slots ----
    #pragma unroll
    for (int gg = 0; gg < 4; gg++) {
        if (g == gg) {
            #pragma unroll
            for (int i = 0; i < 8; i++) {
                int r = tr * 8 + i;
                int sw = (r >> 3) & 7;  // == tr
                float4 w0 = make_float4(o_[i][0], o_[i][1], o_[i][2], o_[i][3]);
                float4 w1 = make_float4(o_[i][4], o_[i][5], o_[i][6], o_[i][7]);
                float* b0 = Qs + r * 64 + (((2 * td)     ^ sw) * 4);
                float* b1 = Qs + r * 64 + (((2 * td + 1) ^ sw) * 4);
                if (gg == 0) {
                    *(float4*)b0 = w0;
                    *(float4*)b1 = w1;
                } else {
                    float4 c0 = *(float4*)b0, c1 = *(float4*)b1;
                    c0.x += w0.x; c0.y += w0.y; c0.z += w0.z; c0.w += w0.w;
                    c1.x += w1.x; c1.y += w1.y; c1.z += w1.z; c1.w += w1.w;
                    *(float4*)b0 = c0;
                    *(float4*)b1 = c1;
                }
            }
        }
        __syncthreads();
    }

    // ---- epilogue: out = Os / den ----
    float* ob = out + ((size_t)(b * Lq + q0)) * CDIM + h * D;
    #pragma unroll
    for (int i = 0; i < 4; i++) {
        int s = t + 256 * i;
        int r = s >> 4, d4 = s & 15;
        int sw = (r >> 3) & 7;
        float4 val = *(float4*)(Qs + r * 64 + ((d4 ^ sw) * 4));
        float inv = 1.0f / denS[r];
        val.x *= inv; val.y *= inv; val.z *= inv; val.w *= inv;
        *(float4*)(ob + (size_t)r * CDIM + d4 * 4) = val;
    }
}

// ---------------- launch ----------------
extern "C" void kernel_launch(void* const* d_in, const int* in_sizes, int n_in,
                              void* d_out, int out_size)
{
    const float* q  = (const float*)d_in[0];
    const float* k  = (const float*)d_in[1];
    const float* v  = (const float*)d_in[2];
    const float* Wc = (const float*)d_in[3];
    const float* bc = (const float*)d_in[4];
    const float* cb = (const float*)d_in[5];

    int B    = in_sizes[6];
    int C    = in_sizes[3] / CS;          // 1024
    int Lk   = in_sizes[1] / (B * C);     // 4096
    int Lq   = in_sizes[0] / (B * C);     // 2048
    int nTok = B * Lk;
    (void)C; (void)n_in; (void)out_size;

    zero_counts_kernel<<<(B * KC + 255) / 256, 256>>>(B * KC);
    idx_kernel<<<(nTok + 63) / 64, 256>>>(k, Wc, bc, Lk, nTok);
    scan_kernel<<<1, 256>>>(B, Lk);
    scatter_kernel<<<(nTok + 255) / 256, 256>>>(Lk, nTok);
    codk_kernel<<<KC, 256>>>(cb);
    gather_kernel<<<B * KC, 256>>>(v);

    size_t smem = SM_FLOATS * sizeof(float);   // ~157 KB
    cudaFuncSetAttribute(attn_kernel,
                         cudaFuncAttributeMaxDynamicSharedMemorySize, (int)smem);
    dim3 grid(Lq / 64, NH, B);
    attn_kernel<<<grid, 256, smem>>>(q, (float*)d_out, Lq);
}

// round 3
// speedup vs baseline: 2.2066x; 2.2066x over previous
#include <cuda_runtime.h>
#include <math.h>
#include <stdint.h>

#define CS    8
#define KC    256
#define NH    16
#define D     64
#define CDIM  1024
#define MAXB  8
#define MAXLK 4096
#define MAXTOK (MAXB*MAXLK)

// ---------------- device scratch ----------------
__device__ int   g_idx[MAXTOK];
__device__ int   g_counts[MAXB*KC];
__device__ int   g_offsets[MAXB*KC];
__device__ int   g_cursor[MAXB*KC];
__device__ int   g_perm[MAXTOK];
__device__ float g_codv[MAXB*KC*CDIM];          // [b][bucket][C]      8 MB
__device__ float g_codvt[MAXB*NH*D*KC];         // [b][h][d][bucket]   8 MB
__device__ float g_codk[NH*KC*D];               // [h][bucket][d]      1 MB

// ---------------- helpers ----------------
__device__ __forceinline__ uint32_t cvt_tf32(float x) {
    uint32_t u; asm("cvt.rn.tf32.f32 %0, %1;" : "=r"(u) : "f"(x)); return u;
}
__device__ __forceinline__ void mma_tf32(float c[4], const uint32_t a[4],
                                         uint32_t b0, uint32_t b1) {
    asm volatile("mma.sync.aligned.m16n8k8.row.col.f32.tf32.tf32.f32 "
        "{%0,%1,%2,%3}, {%4,%5,%6,%7}, {%8,%9}, {%0,%1,%2,%3};"
        : "+f"(c[0]), "+f"(c[1]), "+f"(c[2]), "+f"(c[3])
        : "r"(a[0]), "r"(a[1]), "r"(a[2]), "r"(a[3]), "r"(b0), "r"(b1));
}

// ---------------- K0: zero counts ----------------
__global__ void zero_counts_kernel(int n) {
    int i = blockIdx.x * blockDim.x + threadIdx.x;
    if (i < n) g_counts[i] = 0;
}

// ---------------- K1: bucket index + histogram ----------------
__global__ void __launch_bounds__(256) idx_kernel(
    const float* __restrict__ k, const float* __restrict__ Wc,
    const float* __restrict__ bc, int Lk, int nTok)
{
    __shared__ float4 sW[CS * (CDIM/4)];
    __shared__ float  sbc[CS];
    int t = threadIdx.x;
    for (int i = t; i < CS * (CDIM/4); i += 256) sW[i] = ((const float4*)Wc)[i];
    if (t < CS) sbc[t] = bc[t];
    __syncthreads();

    int warp = t >> 5, lane = t & 31;
    int rowBase = (blockIdx.x * 8 + warp) * 8;
    for (int rr = 0; rr < 8; rr++) {
        int r = rowBase + rr;
        if (r >= nTok) return;
        const float4* krow = (const float4*)(k + (size_t)r * CDIM);
        float acc[CS];
        #pragma unroll
        for (int j = 0; j < CS; j++) acc[j] = 0.f;
        for (int i = lane; i < CDIM/4; i += 32) {
            float4 kv = krow[i];
            #pragma unroll
            for (int j = 0; j < CS; j++) {
                float4 w = sW[j * (CDIM/4) + i];
                acc[j] += kv.x*w.x + kv.y*w.y + kv.z*w.z + kv.w*w.w;
            }
        }
        #pragma unroll
        for (int j = 0; j < CS; j++) {
            #pragma unroll
            for (int o = 16; o >= 1; o >>= 1)
                acc[j] += __shfl_xor_sync(0xffffffffu, acc[j], o);
        }
        if (lane == 0) {
            int code = 0;
            #pragma unroll
            for (int j = 0; j < CS; j++)
                if (acc[j] + sbc[j] >= 0.f) code |= (1 << (7 - j));
            g_idx[r] = code;
            int b = r / Lk;
            atomicAdd(&g_counts[b * KC + code], 1);
        }
    }
}

// ---------------- K2: per-batch scan ----------------
__global__ void scan_kernel(int B, int Lk) {
    __shared__ int s[KC];
    int t = threadIdx.x;
    for (int b = 0; b < B; b++) {
        int v = g_counts[b * KC + t];
        s[t] = v;
        __syncthreads();
        for (int o = 1; o < KC; o <<= 1) {
            int x = (t >= o) ? s[t - o] : 0;
            __syncthreads();
            s[t] += x;
            __syncthreads();
        }
        int off = b * Lk + (s[t] - v);
        g_offsets[b * KC + t] = off;
        g_cursor[b * KC + t]  = off;
        __syncthreads();
    }
}

// ---------------- K3: scatter ----------------
__global__ void scatter_kernel(int Lk, int nTok) {
    int r = blockIdx.x * blockDim.x + threadIdx.x;
    if (r >= nTok) return;
    int b = r / Lk;
    int code = g_idx[r];
    int pos = atomicAdd(&g_cursor[b * KC + code], 1);
    g_perm[pos] = r;
}

// ---------------- K4: codebook keys, head-major [h][bucket][d] ----------------
__global__ void codk_kernel(const float* __restrict__ cb) {
    int c = blockIdx.x, t = threadIdx.x;
    float4 acc = make_float4(0.f, 0.f, 0.f, 0.f);
    #pragma unroll
    for (int j = 0; j < CS; j++) {
        int sel = ((c >> (7 - j)) & 1) ? j : (CS + j);
        float4 w = ((const float4*)cb)[sel * (CDIM/4) + t];
        acc.x += w.x; acc.y += w.y; acc.z += w.z; acc.w += w.w;
    }
    ((float4*)g_codk)[((t >> 4) * KC + c) * (D/4) + (t & 15)] = acc;
}

// ---------------- K5: gather-sum v per bucket ----------------
__global__ void __launch_bounds__(256) gather_kernel(const float* __restrict__ v) {
    int bk = blockIdx.x;
    int t0 = g_offsets[bk];
    int cnt = g_counts[bk];
    __shared__ int toks[1024];
    int t = threadIdx.x;
    int n = min(cnt, 1024);
    for (int i = t; i < n; i += 256) toks[i] = g_perm[t0 + i];
    __syncthreads();
    if (t == 0 && n > 1) {
        for (int i = 1; i < n; i++) {
            int key = toks[i]; int j = i - 1;
            while (j >= 0 && toks[j] > key) { toks[j + 1] = toks[j]; j--; }
            toks[j + 1] = key;
        }
    }
    __syncthreads();
    float4 acc = make_float4(0.f, 0.f, 0.f, 0.f);
    for (int i = 0; i < cnt; i++) {
        int row = (i < n) ? toks[i] : g_perm[t0 + i];
        float4 x = *(const float4*)(v + (size_t)row * CDIM + t * 4);
        acc.x += x.x; acc.y += x.y; acc.z += x.z; acc.w += x.w;
    }
    *(float4*)(g_codv + (size_t)bk * CDIM + t * 4) = acc;
}

// ---------------- K5b: transpose cod_v -> [b][h][d][bucket] ----------------
__global__ void __launch_bounds__(256) transpose_kernel() {
    extern __shared__ float ts[];   // [256][65]
    int bh = blockIdx.x;
    int b = bh >> 4, h = bh & 15;
    int t = threadIdx.x;
    const float* src = g_codv + (size_t)b * KC * CDIM + h * D;
    #pragma unroll
    for (int i = 0; i < 16; i++) {
        int s = i * 256 + t;
        int kk = s >> 4, c4 = s & 15;
        float4 x = *(const float4*)(src + (size_t)kk * CDIM + c4 * 4);
        ts[kk * 65 + c4*4 + 0] = x.x;
        ts[kk * 65 + c4*4 + 1] = x.y;
        ts[kk * 65 + c4*4 + 2] = x.z;
        ts[kk * 65 + c4*4 + 3] = x.w;
    }
    __syncthreads();
    float* dst = g_codvt + (size_t)bh * D * KC;
    #pragma unroll
    for (int i = 0; i < 16; i++) {
        int s = i * 256 + t;
        int d = s >> 6, k4 = s & 63;
        float4 w = make_float4(ts[(k4*4+0)*65 + d], ts[(k4*4+1)*65 + d],
                               ts[(k4*4+2)*65 + d], ts[(k4*4+3)*65 + d]);
        *(float4*)(dst + (size_t)d * KC + k4 * 4) = w;
    }
}

// ---------------- K6: mma.sync tf32 bucketed attention ----------------
// grid(NH, B), 256 threads = 8 warps (16 q-rows each), K/V resident in smem.
// Ksm packed: bucket n, j(0..3), q(0..3): uint4 {K[n][16q+j], +4, +8, +12}
//   at uint4 index (n*4+j)*5 + q   (stride 5 kills LDS.128 phase conflicts)
// Vsm packed: dim n, chunk ch, j: uint4 {VT[n][16ch+j], +4, +8, +12}
//   at uint4 index n*68 + ch*4 + j (stride 68 ≡ 4 mod 8)
#define K_OFF   0
#define V_OFF   81920
#define CNT_OFF 151552
#define SM_TOT  152576

__global__ void __launch_bounds__(256, 1) attn_kernel(
    const float* __restrict__ q, float* __restrict__ out, int Lq)
{
    extern __shared__ char sm[];
    uint32_t* Ksm = (uint32_t*)(sm + K_OFF);
    uint32_t* Vsm = (uint32_t*)(sm + V_OFF);
    float*    cntS = (float*)(sm + CNT_OFF);

    const int t = threadIdx.x, lane = t & 31, w = t >> 5;
    const int h = blockIdx.x, b = blockIdx.y;
    const int j = lane & 3, g = lane >> 2;

    // ---- pack K into smem ----
    const float4* ksrc = (const float4*)(g_codk + (size_t)h * KC * D);
    #pragma unroll
    for (int i = 0; i < 16; i++) {
        int s = t + 256 * i;
        int n = s >> 4, m = s & 15;
        float4 x = ksrc[s];
        int base4 = (n * 4) * 5 + (m >> 2);
        int sl = ((m >> 1) & 1) * 2 + (m & 1);
        Ksm[(base4 + 0*5)*4 + sl] = cvt_tf32(x.x);
        Ksm[(base4 + 1*5)*4 + sl] = cvt_tf32(x.y);
        Ksm[(base4 + 2*5)*4 + sl] = cvt_tf32(x.z);
        Ksm[(base4 + 3*5)*4 + sl] = cvt_tf32(x.w);
    }
    // ---- pack V^T into smem ----
    const float4* vsrc = (const float4*)(g_codvt + (size_t)(b * NH + h) * D * KC);
    #pragma unroll
    for (int i = 0; i < 16; i++) {
        int s = t + 256 * i;
        int n = s >> 6, m = s & 63;
        float4 x = vsrc[s];
        int base4 = n * 68 + (m >> 2) * 4;
        int sl = m & 3;
        Vsm[(base4 + 0)*4 + sl] = cvt_tf32(x.x);
        Vsm[(base4 + 1)*4 + sl] = cvt_tf32(x.y);
        Vsm[(base4 + 2)*4 + sl] = cvt_tf32(x.z);
        Vsm[(base4 + 3)*4 + sl] = cvt_tf32(x.w);
    }
    cntS[t] = (float)g_counts[b * KC + t];
    __syncthreads();

    const uint4* KB = (const uint4*)Ksm;
    const uint4* VB = (const uint4*)Vsm;
    const int srcA = (lane & ~3) | (j >> 1);
    const int srcB = srcA + 2;
    const bool odd = (j & 1) != 0;

    for (int q0 = 0; q0 < Lq; q0 += 128) {
        // ---- Q A-fragments straight from gmem (scale + tf32 fold) ----
        const float* qr0 = q + (size_t)(b * Lq + q0 + w * 16 + g) * CDIM + h * D;
        const float* qr8 = qr0 + 8 * CDIM;
        uint32_t qa[8][4];
        #pragma unroll
        for (int kc = 0; kc < 8; kc++) {
            qa[kc][0] = cvt_tf32(qr0[kc*8 + j]     * 0.125f);
            qa[kc][1] = cvt_tf32(qr8[kc*8 + j]     * 0.125f);
            qa[kc][2] = cvt_tf32(qr0[kc*8 + j + 4] * 0.125f);
            qa[kc][3] = cvt_tf32(qr8[kc*8 + j + 4] * 0.125f);
        }

        float O[8][4];
        #pragma unroll
        for (int nb = 0; nb < 8; nb++) {
            O[nb][0] = 0.f; O[nb][1] = 0.f; O[nb][2] = 0.f; O[nb][3] = 0.f;
        }
        float den0 = 0.f, den1 = 0.f;

        #pragma unroll 1
        for (int ch = 0; ch < 16; ch++) {
            // ---- S = Q @ K^T for 16 buckets ----
            uint4 kf0[4], kf1[4];
            int nr0 = ch * 16 + g, nr1 = nr0 + 8;
            #pragma unroll
            for (int qq = 0; qq < 4; qq++) {
                kf0[qq] = KB[(nr0*4 + j)*5 + qq];
                kf1[qq] = KB[(nr1*4 + j)*5 + qq];
            }
            float s0[4] = {0.f,0.f,0.f,0.f}, s1[4] = {0.f,0.f,0.f,0.f};
            #pragma unroll
            for (int kc = 0; kc < 8; kc++) {
                uint4 f0 = kf0[kc >> 1], f1 = kf1[kc >> 1];
                uint32_t b00 = (kc & 1) ? f0.z : f0.x;
                uint32_t b01 = (kc & 1) ? f0.w : f0.y;
                uint32_t b10 = (kc & 1) ? f1.z : f1.x;
                uint32_t b11 = (kc & 1) ? f1.w : f1.y;
                mma_tf32(s0, qa[kc], b00, b01);
                mma_tf32(s1, qa[kc], b10, b11);
            }

            // ---- p = mask * exp(s); den accumulation ----
            float2 c0 = *(const float2*)(cntS + ch*16 + 2*j);
            float2 c1 = *(const float2*)(cntS + ch*16 + 8 + 2*j);
            float p00 = c0.x > 0.f ? __expf(s0[0]) : 0.f;
            float p01 = c0.y > 0.f ? __expf(s0[1]) : 0.f;
            float p02 = c0.x > 0.f ? __expf(s0[2]) : 0.f;
            float p03 = c0.y > 0.f ? __expf(s0[3]) : 0.f;
            float p10 = c1.x > 0.f ? __expf(s1[0]) : 0.f;
            float p11 = c1.y > 0.f ? __expf(s1[1]) : 0.f;
            float p12 = c1.x > 0.f ? __expf(s1[2]) : 0.f;
            float p13 = c1.y > 0.f ? __expf(s1[3]) : 0.f;
            den0 += p00*c0.x + p01*c0.y + p10*c1.x + p11*c1.y;
            den1 += p02*c0.x + p03*c0.y + p12*c1.x + p13*c1.y;

            uint32_t u00 = cvt_tf32(p00), u01 = cvt_tf32(p01);
            uint32_t u02 = cvt_tf32(p02), u03 = cvt_tf32(p03);
            uint32_t u10 = cvt_tf32(p10), u11 = cvt_tf32(p11);
            uint32_t u12 = cvt_tf32(p12), u13 = cvt_tf32(p13);

            // ---- C-frag -> A-frag layout conversion via shuffles ----
            uint32_t A0[4], A1[4];
            {
                uint32_t x0 = __shfl_sync(0xffffffffu, u00, srcA);
                uint32_t x1 = __shfl_sync(0xffffffffu, u01, srcA);
                uint32_t y0 = __shfl_sync(0xffffffffu, u00, srcB);
                uint32_t y1 = __shfl_sync(0xffffffffu, u01, srcB);
                uint32_t z0 = __shfl_sync(0xffffffffu, u02, srcA);
                uint32_t z1 = __shfl_sync(0xffffffffu, u03, srcA);
                uint32_t w0 = __shfl_sync(0xffffffffu, u02, srcB);
                uint32_t w1 = __shfl_sync(0xffffffffu, u03, srcB);
                A0[0] = odd ? x1 : x0;  A0[1] = odd ? z1 : z0;
                A0[2] = odd ? y1 : y0;  A0[3] = odd ? w1 : w0;
            }
            {
                uint32_t x0 = __shfl_sync(0xffffffffu, u10, srcA);
                uint32_t x1 = __shfl_sync(0xffffffffu, u11, srcA);
                uint32_t y0 = __shfl_sync(0xffffffffu, u10, srcB);
                uint32_t y1 = __shfl_sync(0xffffffffu, u11, srcB);
                uint32_t z0 = __shfl_sync(0xffffffffu, u12, srcA);
                uint32_t z1 = __shfl_sync(0xffffffffu, u13, srcA);
                uint32_t w0 = __shfl_sync(0xffffffffu, u12, srcB);
                uint32_t w1 = __shfl_sync(0xffffffffu, u13, srcB);
                A1[0] = odd ? x1 : x0;  A1[1] = odd ? z1 : z0;
                A1[2] = odd ? y1 : y0;  A1[3] = odd ? w1 : w0;
            }

            // ---- O += P @ V ----
            #pragma unroll
            for (int nbk = 0; nbk < 8; nbk++) {
                uint4 vv = VB[(nbk*8 + g)*68 + ch*4 + j];
                mma_tf32(O[nbk], A0, vv.x, vv.y);
                mma_tf32(O[nbk], A1, vv.z, vv.w);
            }
        }

        // ---- reduce den across the 4 lanes of each row-quad ----
        den0 += __shfl_xor_sync(0xffffffffu, den0, 1);
        den0 += __shfl_xor_sync(0xffffffffu, den0, 2);
        den1 += __shfl_xor_sync(0xffffffffu, den1, 1);
        den1 += __shfl_xor_sync(0xffffffffu, den1, 2);
        float inv0 = 1.0f / den0;
        float inv1 = 1.0f / den1;

        // ---- epilogue ----
        float* ob0 = out + (size_t)(b * Lq + q0 + w * 16 + g) * CDIM + h * D;
        float* ob8 = ob0 + 8 * CDIM;
        #pragma unroll
        for (int nbk = 0; nbk < 8; nbk++) {
            float2 r0 = make_float2(O[nbk][0] * inv0, O[nbk][1] * inv0);
            float2 r1 = make_float2(O[nbk][2] * inv1, O[nbk][3] * inv1);
            *(float2*)(ob0 + nbk*8 + 2*j) = r0;
            *(float2*)(ob8 + nbk*8 + 2*j) = r1;
        }
    }
}

// ---------------- launch ----------------
extern "C" void kernel_launch(void* const* d_in, const int* in_sizes, int n_in,
                              void* d_out, int out_size)
{
    const float* q  = (const float*)d_in[0];
    const float* k  = (const float*)d_in[1];
    const float* v  = (const float*)d_in[2];
    const float* Wc = (const float*)d_in[3];
    const float* bc = (const float*)d_in[4];
    const float* cb = (const float*)d_in[5];

    int B    = in_sizes[6];
    int C    = in_sizes[3] / CS;
    int Lk   = in_sizes[1] / (B * C);
    int Lq   = in_sizes[0] / (B * C);
    int nTok = B * Lk;
    (void)n_in; (void)out_size;

    zero_counts_kernel<<<(B * KC + 255) / 256, 256>>>(B * KC);
    idx_kernel<<<(nTok + 63) / 64, 256>>>(k, Wc, bc, Lk, nTok);
    scan_kernel<<<1, 256>>>(B, Lk);
    scatter_kernel<<<(nTok + 255) / 256, 256>>>(Lk, nTok);
    codk_kernel<<<KC, 256>>>(cb);
    gather_kernel<<<B * KC, 256>>>(v);

    size_t tsm = 256 * 65 * sizeof(float);
    cudaFuncSetAttribute(transpose_kernel,
                         cudaFuncAttributeMaxDynamicSharedMemorySize, (int)tsm);
    transpose_kernel<<<B * NH, 256, tsm>>>();

    cudaFuncSetAttribute(attn_kernel,
                         cudaFuncAttributeMaxDynamicSharedMemorySize, SM_TOT);
    dim3 grid(NH, B);
    attn_kernel<<<grid, 256, SM_TOT>>>(q, (float*)d_out, Lq);
}

// round 4
// speedup vs baseline: 2.8095x; 1.2732x over previous
#include <cuda_runtime.h>
#include <cuda_fp16.h>
#include <math.h>
#include <stdint.h>

#define CS    8
#define KC    256
#define NH    16
#define D     64
#define CDIM  1024
#define MAXB  8
#define MAXLK 4096
#define MAXTOK (MAXB*MAXLK)

// ---------------- device scratch ----------------
__device__ int   g_idx[MAXTOK];
__device__ int   g_counts[MAXB*KC];
__device__ int   g_offsets[MAXB*KC];
__device__ int   g_cursor[MAXB*KC];
__device__ int   g_perm[MAXTOK];
__device__ float g_codv[MAXB*KC*CDIM];          // [b][bucket][C]      8 MB
__device__ float g_codvt[MAXB*NH*D*KC];         // [b][h][d][bucket]   8 MB
__device__ float g_codk[NH*KC*D];               // [h][bucket][d]      1 MB

// ---------------- helpers ----------------
__device__ __forceinline__ uint32_t pack_h2(float a, float b) {
    __half2 h = __floats2half2_rn(a, b);
    return *(uint32_t*)&h;
}
__device__ __forceinline__ void mma_f16(float c[4], const uint32_t a[4],
                                        uint32_t b0, uint32_t b1) {
    asm volatile("mma.sync.aligned.m16n8k16.row.col.f32.f16.f16.f32 "
        "{%0,%1,%2,%3}, {%4,%5,%6,%7}, {%8,%9}, {%0,%1,%2,%3};"
        : "+f"(c[0]), "+f"(c[1]), "+f"(c[2]), "+f"(c[3])
        : "r"(a[0]), "r"(a[1]), "r"(a[2]), "r"(a[3]), "r"(b0), "r"(b1));
}

// ---------------- K0: zero counts ----------------
__global__ void zero_counts_kernel(int n) {
    int i = blockIdx.x * blockDim.x + threadIdx.x;
    if (i < n) g_counts[i] = 0;
}

// ---------------- K1: bucket index + histogram ----------------
__global__ void __launch_bounds__(256) idx_kernel(
    const float* __restrict__ k, const float* __restrict__ Wc,
    const float* __restrict__ bc, int Lk, int nTok)
{
    __shared__ float4 sW[CS * (CDIM/4)];
    __shared__ float  sbc[CS];
    int t = threadIdx.x;
    for (int i = t; i < CS * (CDIM/4); i += 256) sW[i] = ((const float4*)Wc)[i];
    if (t < CS) sbc[t] = bc[t];
    __syncthreads();

    int warp = t >> 5, lane = t & 31;
    int rowBase = (blockIdx.x * 8 + warp) * 8;
    for (int rr = 0; rr < 8; rr++) {
        int r = rowBase + rr;
        if (r >= nTok) return;
        const float4* krow = (const float4*)(k + (size_t)r * CDIM);
        float acc[CS];
        #pragma unroll
        for (int j = 0; j < CS; j++) acc[j] = 0.f;
        for (int i = lane; i < CDIM/4; i += 32) {
            float4 kv = krow[i];
            #pragma unroll
            for (int j = 0; j < CS; j++) {
                float4 w = sW[j * (CDIM/4) + i];
                acc[j] += kv.x*w.x + kv.y*w.y + kv.z*w.z + kv.w*w.w;
            }
        }
        #pragma unroll
        for (int j = 0; j < CS; j++) {
            #pragma unroll
            for (int o = 16; o >= 1; o >>= 1)
                acc[j] += __shfl_xor_sync(0xffffffffu, acc[j], o);
        }
        if (lane == 0) {
            int code = 0;
            #pragma unroll
            for (int j = 0; j < CS; j++)
                if (acc[j] + sbc[j] >= 0.f) code |= (1 << (7 - j));
            g_idx[r] = code;
            int b = r / Lk;
            atomicAdd(&g_counts[b * KC + code], 1);
        }
    }
}

// ---------------- K2: per-batch scan ----------------
__global__ void scan_kernel(int B, int Lk) {
    __shared__ int s[KC];
    int t = threadIdx.x;
    for (int b = 0; b < B; b++) {
        int v = g_counts[b * KC + t];
        s[t] = v;
        __syncthreads();
        for (int o = 1; o < KC; o <<= 1) {
            int x = (t >= o) ? s[t - o] : 0;
            __syncthreads();
            s[t] += x;
            __syncthreads();
        }
        int off = b * Lk + (s[t] - v);
        g_offsets[b * KC + t] = off;
        g_cursor[b * KC + t]  = off;
        __syncthreads();
    }
}

// ---------------- K3: scatter ----------------
__global__ void scatter_kernel(int Lk, int nTok) {
    int r = blockIdx.x * blockDim.x + threadIdx.x;
    if (r >= nTok) return;
    int b = r / Lk;
    int code = g_idx[r];
    int pos = atomicAdd(&g_cursor[b * KC + code], 1);
    g_perm[pos] = r;
}

// ---------------- K4: codebook keys, head-major [h][bucket][d] ----------------
__global__ void codk_kernel(const float* __restrict__ cb) {
    int c = blockIdx.x, t = threadIdx.x;
    float4 acc = make_float4(0.f, 0.f, 0.f, 0.f);
    #pragma unroll
    for (int j = 0; j < CS; j++) {
        int sel = ((c >> (7 - j)) & 1) ? j : (CS + j);
        float4 w = ((const float4*)cb)[sel * (CDIM/4) + t];
        acc.x += w.x; acc.y += w.y; acc.z += w.z; acc.w += w.w;
    }
    ((float4*)g_codk)[((t >> 4) * KC + c) * (D/4) + (t & 15)] = acc;
}

// ---------------- K5: gather-sum v per bucket ----------------
__global__ void __launch_bounds__(256) gather_kernel(const float* __restrict__ v) {
    int bk = blockIdx.x;
    int t0 = g_offsets[bk];
    int cnt = g_counts[bk];
    __shared__ int toks[1024];
    int t = threadIdx.x;
    int n = min(cnt, 1024);
    for (int i = t; i < n; i += 256) toks[i] = g_perm[t0 + i];
    __syncthreads();
    if (t == 0 && n > 1) {
        for (int i = 1; i < n; i++) {
            int key = toks[i]; int j = i - 1;
            while (j >= 0 && toks[j] > key) { toks[j + 1] = toks[j]; j--; }
            toks[j + 1] = key;
        }
    }
    __syncthreads();
    float4 acc = make_float4(0.f, 0.f, 0.f, 0.f);
    for (int i = 0; i < cnt; i++) {
        int row = (i < n) ? toks[i] : g_perm[t0 + i];
        float4 x = *(const float4*)(v + (size_t)row * CDIM + t * 4);
        acc.x += x.x; acc.y += x.y; acc.z += x.z; acc.w += x.w;
    }
    *(float4*)(g_codv + (size_t)bk * CDIM + t * 4) = acc;
}

// ---------------- K5b: transpose cod_v -> [b][h][d][bucket] ----------------
__global__ void __launch_bounds__(256) transpose_kernel() {
    extern __shared__ float ts[];   // [256][65]
    int bh = blockIdx.x;
    int b = bh >> 4, h = bh & 15;
    int t = threadIdx.x;
    const float* src = g_codv + (size_t)b * KC * CDIM + h * D;
    #pragma unroll
    for (int i = 0; i < 16; i++) {
        int s = i * 256 + t;
        int kk = s >> 4, c4 = s & 15;
        float4 x = *(const float4*)(src + (size_t)kk * CDIM + c4 * 4);
        ts[kk * 65 + c4*4 + 0] = x.x;
        ts[kk * 65 + c4*4 + 1] = x.y;
        ts[kk * 65 + c4*4 + 2] = x.z;
        ts[kk * 65 + c4*4 + 3] = x.w;
    }
    __syncthreads();
    float* dst = g_codvt + (size_t)bh * D * KC;
    #pragma unroll
    for (int i = 0; i < 16; i++) {
        int s = i * 256 + t;
        int d = s >> 6, k4 = s & 63;
        float4 w = make_float4(ts[(k4*4+0)*65 + d], ts[(k4*4+1)*65 + d],
                               ts[(k4*4+2)*65 + d], ts[(k4*4+3)*65 + d]);
        *(float4*)(dst + (size_t)d * KC + k4 * 4) = w;
    }
}

// ---------------- K6: fp16 m16n8k16 bucketed attention ----------------
// grid(NH, B), 256 threads = 8 warps (16 q-rows each), K/V fp16 resident in smem.
//
// Ksm (B-frags for S): per (bucket n, j): 2 uint4 at index (n*4+j)*3 + slot.
//   slot s, comp c: kc = 2s + (c>>1), w = c&1 -> half2 of dims (16kc+8w+2j, +1).
//   LDS.128 phase conflict-free (j stride 48B, n stride 192B mod 128 covers all banks).
// Vsm (B-frags for PV): per (ch, j, g): 4 uint4 at index (ch*4+j)*33 + g*4 + s.
//   slot s comp c: nbk = 2s + (c>>1), w = c&1 -> half2 of buckets (ch*16+8w+2j, +1)
//   for dim col nbk*8+g. Stride 33 -> conflict-free phases.
#define K_OFF   0
#define K_U4    (KC*4*3)                    // 3072 uint4 = 49152 B
#define V_OFF   (K_U4*16)
#define V_U4    (16*4*33)                   // 2112 uint4 = 33792 B
#define CNT_OFF (V_OFF + V_U4*16)
#define SM_TOT  (CNT_OFF + KC*4)

__global__ void __launch_bounds__(256, 1) attn_kernel(
    const float* __restrict__ q, float* __restrict__ out, int Lq)
{
    extern __shared__ char sm[];
    uint32_t* Ksm = (uint32_t*)(sm + K_OFF);
    uint32_t* Vsm = (uint32_t*)(sm + V_OFF);
    float*    cntS = (float*)(sm + CNT_OFF);

    const int t = threadIdx.x, lane = t & 31, w = t >> 5;
    const int h = blockIdx.x, b = blockIdx.y;
    const int j = lane & 3, g = lane >> 2;

    // ---- pack K (fp16 B-frag layout) ----
    const float2* ksrc2 = (const float2*)(g_codk + (size_t)h * KC * D);
    #pragma unroll
    for (int i = 0; i < 32; i++) {
        int s = t + 256 * i;              // 8192 float2
        int n = s >> 5, p = s & 31;
        float2 x = ksrc2[s];
        int jj = p & 3, qq = p >> 2;      // qq = 2*kc + w
        int kc = qq >> 1, ww = qq & 1;
        int slot = kc >> 1, c = ((kc & 1) << 1) | ww;
        Ksm[((n*4 + jj)*3 + slot)*4 + c] = pack_h2(x.x, x.y);
    }
    // ---- pack V^T (fp16 B-frag layout) ----
    const float2* vsrc2 = (const float2*)(g_codvt + (size_t)(b * NH + h) * D * KC);
    #pragma unroll
    for (int i = 0; i < 32; i++) {
        int s = t + 256 * i;              // 8192 float2 : d = s>>7, pair p = s&127
        int d = s >> 7, p = s & 127;
        float2 x = vsrc2[s];
        int ch = p >> 3, r = p & 7;
        int jj = r & 3, ww = r >> 2;
        int nbk = d >> 3, gg = d & 7;
        int slot = nbk >> 1, c = ((nbk & 1) << 1) | ww;
        Vsm[(((ch*4 + jj)*33) + gg*4 + slot)*4 + c] = pack_h2(x.x, x.y);
    }
    cntS[t] = (float)g_counts[b * KC + t];
    __syncthreads();

    const uint4* KB = (const uint4*)Ksm;
    const uint4* VB = (const uint4*)Vsm;

    for (int q0 = 0; q0 < Lq; q0 += 128) {
        // ---- Q A-fragments (scale folded, fp16) ----
        const float* qr0 = q + (size_t)(b * Lq + q0 + w * 16 + g) * CDIM + h * D;
        const float* qr8 = qr0 + 8 * CDIM;
        uint32_t qa[4][4];
        #pragma unroll
        for (int kc = 0; kc < 4; kc++) {
            float2 x0 = *(const float2*)(qr0 + kc*16 + 2*j);
            float2 x1 = *(const float2*)(qr8 + kc*16 + 2*j);
            float2 x2 = *(const float2*)(qr0 + kc*16 + 8 + 2*j);
            float2 x3 = *(const float2*)(qr8 + kc*16 + 8 + 2*j);
            qa[kc][0] = pack_h2(x0.x * 0.125f, x0.y * 0.125f);
            qa[kc][1] = pack_h2(x1.x * 0.125f, x1.y * 0.125f);
            qa[kc][2] = pack_h2(x2.x * 0.125f, x2.y * 0.125f);
            qa[kc][3] = pack_h2(x3.x * 0.125f, x3.y * 0.125f);
        }

        float O[8][4];
        #pragma unroll
        for (int nb = 0; nb < 8; nb++) {
            O[nb][0] = 0.f; O[nb][1] = 0.f; O[nb][2] = 0.f; O[nb][3] = 0.f;
        }
        float den0 = 0.f, den1 = 0.f;

        #pragma unroll 1
        for (int ch = 0; ch < 16; ch++) {
            // ---- S = Q @ K^T : buckets [ch*16, ch*16+16) ----
            int nr0 = ch * 16 + g, nr1 = nr0 + 8;
            uint4 ka0 = KB[(nr0*4 + j)*3 + 0];
            uint4 ka1 = KB[(nr0*4 + j)*3 + 1];
            uint4 kb0 = KB[(nr1*4 + j)*3 + 0];
            uint4 kb1 = KB[(nr1*4 + j)*3 + 1];
            float slo[4] = {0.f,0.f,0.f,0.f}, shi[4] = {0.f,0.f,0.f,0.f};
            mma_f16(slo, qa[0], ka0.x, ka0.y);
            mma_f16(slo, qa[1], ka0.z, ka0.w);
            mma_f16(slo, qa[2], ka1.x, ka1.y);
            mma_f16(slo, qa[3], ka1.z, ka1.w);
            mma_f16(shi, qa[0], kb0.x, kb0.y);
            mma_f16(shi, qa[1], kb0.z, kb0.w);
            mma_f16(shi, qa[2], kb1.x, kb1.y);
            mma_f16(shi, qa[3], kb1.z, kb1.w);

            // ---- p = mask * exp(s), den += p*cnt ----
            float2 c0 = *(const float2*)(cntS + ch*16 + 2*j);
            float2 c1 = *(const float2*)(cntS + ch*16 + 8 + 2*j);
            float plo0 = c0.x > 0.f ? __expf(slo[0]) : 0.f;
            float plo1 = c0.y > 0.f ? __expf(slo[1]) : 0.f;
            float plo2 = c0.x > 0.f ? __expf(slo[2]) : 0.f;
            float plo3 = c0.y > 0.f ? __expf(slo[3]) : 0.f;
            float phi0 = c1.x > 0.f ? __expf(shi[0]) : 0.f;
            float phi1 = c1.y > 0.f ? __expf(shi[1]) : 0.f;
            float phi2 = c1.x > 0.f ? __expf(shi[2]) : 0.f;
            float phi3 = c1.y > 0.f ? __expf(shi[3]) : 0.f;
            den0 += plo0*c0.x + plo1*c0.y + phi0*c1.x + phi1*c1.y;
            den1 += plo2*c0.x + plo3*c0.y + phi2*c1.x + phi3*c1.y;

            // ---- C-frag == A-frag for k16 PV: no shuffles ----
            uint32_t A[4];
            A[0] = pack_h2(plo0, plo1);   // row g,   k = 2j,2j+1
            A[1] = pack_h2(plo2, plo3);   // row g+8, k = 2j,2j+1
            A[2] = pack_h2(phi0, phi1);   // row g,   k = 8+2j
            A[3] = pack_h2(phi2, phi3);   // row g+8, k = 8+2j

            // ---- O += P @ V ----
            const uint4* vrow = VB + (ch*4 + j)*33 + g*4;
            #pragma unroll
            for (int s = 0; s < 4; s++) {
                uint4 vv = vrow[s];
                mma_f16(O[2*s],     A, vv.x, vv.y);
                mma_f16(O[2*s + 1], A, vv.z, vv.w);
            }
        }

        // ---- reduce den across the 4 lanes of each row-quad ----
        den0 += __shfl_xor_sync(0xffffffffu, den0, 1);
        den0 += __shfl_xor_sync(0xffffffffu, den0, 2);
        den1 += __shfl_xor_sync(0xffffffffu, den1, 1);
        den1 += __shfl_xor_sync(0xffffffffu, den1, 2);
        float inv0 = 1.0f / den0;
        float inv1 = 1.0f / den1;

        // ---- epilogue ----
        float* ob0 = out + (size_t)(b * Lq + q0 + w * 16 + g) * CDIM + h * D;
        float* ob8 = ob0 + 8 * CDIM;
        #pragma unroll
        for (int nbk = 0; nbk < 8; nbk++) {
            float2 r0 = make_float2(O[nbk][0] * inv0, O[nbk][1] * inv0);
            float2 r1 = make_float2(O[nbk][2] * inv1, O[nbk][3] * inv1);
            *(float2*)(ob0 + nbk*8 + 2*j) = r0;
            *(float2*)(ob8 + nbk*8 + 2*j) = r1;
        }
    }
}

// ---------------- launch ----------------
extern "C" void kernel_launch(void* const* d_in, const int* in_sizes, int n_in,
                              void* d_out, int out_size)
{
    const float* q  = (const float*)d_in[0];
    const float* k  = (const float*)d_in[1];
    const float* v  = (const float*)d_in[2];
    const float* Wc = (const float*)d_in[3];
    const float* bc = (const float*)d_in[4];
    const float* cb = (const float*)d_in[5];

    int B    = in_sizes[6];
    int C    = in_sizes[3] / CS;
    int Lk   = in_sizes[1] / (B * C);
    int Lq   = in_sizes[0] / (B * C);
    int nTok = B * Lk;
    (void)n_in; (void)out_size;

    zero_counts_kernel<<<(B * KC + 255) / 256, 256>>>(B * KC);
    idx_kernel<<<(nTok + 63) / 64, 256>>>(k, Wc, bc, Lk, nTok);
    scan_kernel<<<1, 256>>>(B, Lk);
    scatter_kernel<<<(nTok + 255) / 256, 256>>>(Lk, nTok);
    codk_kernel<<<KC, 256>>>(cb);
    gather_kernel<<<B * KC, 256>>>(v);

    size_t tsm = 256 * 65 * sizeof(float);
    cudaFuncSetAttribute(transpose_kernel,
                         cudaFuncAttributeMaxDynamicSharedMemorySize, (int)tsm);
    transpose_kernel<<<B * NH, 256, tsm>>>();

    cudaFuncSetAttribute(attn_kernel,
                         cudaFuncAttributeMaxDynamicSharedMemorySize, SM_TOT);
    dim3 grid(NH, B);
    attn_kernel<<<grid, 256, SM_TOT>>>(q, (float*)d_out, Lq);
}

// round 5
// speedup vs baseline: 3.1300x; 1.1141x over previous
#include <cuda_runtime.h>
#include <cuda_fp16.h>
#include <math.h>
#include <stdint.h>

#define CS    8
#define KC    256
#define NH    16
#define D     64
#define CDIM  1024
#define MAXB  8
#define MAXLK 4096
#define MAXTOK (MAXB*MAXLK)

// ---------------- device scratch ----------------
__device__ int   g_idx[MAXTOK];
__device__ int   g_counts[MAXB*KC];
__device__ int   g_offsets[MAXB*KC];
__device__ int   g_cursor[MAXB*KC];
__device__ int   g_perm[MAXTOK];
__device__ float g_codv[MAXB*KC*CDIM];          // [b][bucket][C]      8 MB
__device__ float g_codvt[MAXB*NH*D*KC];         // [b][h][d][bucket]   8 MB
__device__ float g_codk[NH*KC*D];               // [h][bucket][d]      1 MB

// ---------------- helpers ----------------
__device__ __forceinline__ uint32_t pack_h2(float a, float b) {
    __half2 h = __floats2half2_rn(a, b);
    return *(uint32_t*)&h;
}
__device__ __forceinline__ uint32_t hmul2_u(uint32_t a, uint32_t b) {
    __half2 r = __hmul2(*(__half2*)&a, *(__half2*)&b);
    return *(uint32_t*)&r;
}
__device__ __forceinline__ void mma_f16(float c[4], const uint32_t a[4],
                                        uint32_t b0, uint32_t b1) {
    asm volatile("mma.sync.aligned.m16n8k16.row.col.f32.f16.f16.f32 "
        "{%0,%1,%2,%3}, {%4,%5,%6,%7}, {%8,%9}, {%0,%1,%2,%3};"
        : "+f"(c[0]), "+f"(c[1]), "+f"(c[2]), "+f"(c[3])
        : "r"(a[0]), "r"(a[1]), "r"(a[2]), "r"(a[3]), "r"(b0), "r"(b1));
}

// ---------------- K0: zero counts ----------------
__global__ void zero_counts_kernel(int n) {
    int i = blockIdx.x * blockDim.x + threadIdx.x;
    if (i < n) g_counts[i] = 0;
}

// ---------------- K1: bucket index + histogram ----------------
__global__ void __launch_bounds__(256) idx_kernel(
    const float* __restrict__ k, const float* __restrict__ Wc,
    const float* __restrict__ bc, int Lk, int nTok)
{
    __shared__ float4 sW[CS * (CDIM/4)];
    __shared__ float  sbc[CS];
    int t = threadIdx.x;
    for (int i = t; i < CS * (CDIM/4); i += 256) sW[i] = ((const float4*)Wc)[i];
    if (t < CS) sbc[t] = bc[t];
    __syncthreads();

    int warp = t >> 5, lane = t & 31;
    int rowBase = (blockIdx.x * 8 + warp) * 8;
    for (int rr = 0; rr < 8; rr++) {
        int r = rowBase + rr;
        if (r >= nTok) return;
        const float4* krow = (const float4*)(k + (size_t)r * CDIM);
        float acc[CS];
        #pragma unroll
        for (int j = 0; j < CS; j++) acc[j] = 0.f;
        for (int i = lane; i < CDIM/4; i += 32) {
            float4 kv = krow[i];
            #pragma unroll
            for (int j = 0; j < CS; j++) {
                float4 w = sW[j * (CDIM/4) + i];
                acc[j] += kv.x*w.x + kv.y*w.y + kv.z*w.z + kv.w*w.w;
            }
        }
        #pragma unroll
        for (int j = 0; j < CS; j++) {
            #pragma unroll
            for (int o = 16; o >= 1; o >>= 1)
                acc[j] += __shfl_xor_sync(0xffffffffu, acc[j], o);
        }
        if (lane == 0) {
            int code = 0;
            #pragma unroll
            for (int j = 0; j < CS; j++)
                if (acc[j] + sbc[j] >= 0.f) code |= (1 << (7 - j));
            g_idx[r] = code;
            int b = r / Lk;
            atomicAdd(&g_counts[b * KC + code], 1);
        }
    }
}

// ---------------- K2: per-batch scan ----------------
__global__ void scan_kernel(int B, int Lk) {
    __shared__ int s[KC];
    int t = threadIdx.x;
    for (int b = 0; b < B; b++) {
        int v = g_counts[b * KC + t];
        s[t] = v;
        __syncthreads();
        for (int o = 1; o < KC; o <<= 1) {
            int x = (t >= o) ? s[t - o] : 0;
            __syncthreads();
            s[t] += x;
            __syncthreads();
        }
        int off = b * Lk + (s[t] - v);
        g_offsets[b * KC + t] = off;
        g_cursor[b * KC + t]  = off;
        __syncthreads();
    }
}

// ---------------- K3: scatter ----------------
__global__ void scatter_kernel(int Lk, int nTok) {
    int r = blockIdx.x * blockDim.x + threadIdx.x;
    if (r >= nTok) return;
    int b = r / Lk;
    int code = g_idx[r];
    int pos = atomicAdd(&g_cursor[b * KC + code], 1);
    g_perm[pos] = r;
}

// ---------------- K4: codebook keys, head-major [h][bucket][d] ----------------
__global__ void codk_kernel(const float* __restrict__ cb) {
    int c = blockIdx.x, t = threadIdx.x;
    float4 acc = make_float4(0.f, 0.f, 0.f, 0.f);
    #pragma unroll
    for (int j = 0; j < CS; j++) {
        int sel = ((c >> (7 - j)) & 1) ? j : (CS + j);
        float4 w = ((const float4*)cb)[sel * (CDIM/4) + t];
        acc.x += w.x; acc.y += w.y; acc.z += w.z; acc.w += w.w;
    }
    ((float4*)g_codk)[((t >> 4) * KC + c) * (D/4) + (t & 15)] = acc;
}

// ---------------- K5: gather-sum v per bucket ----------------
__global__ void __launch_bounds__(256) gather_kernel(const float* __restrict__ v) {
    int bk = blockIdx.x;
    int t0 = g_offsets[bk];
    int cnt = g_counts[bk];
    __shared__ int toks[1024];
    int t = threadIdx.x;
    int n = min(cnt, 1024);
    for (int i = t; i < n; i += 256) toks[i] = g_perm[t0 + i];
    __syncthreads();
    if (t == 0 && n > 1) {
        for (int i = 1; i < n; i++) {
            int key = toks[i]; int j = i - 1;
            while (j >= 0 && toks[j] > key) { toks[j + 1] = toks[j]; j--; }
            toks[j + 1] = key;
        }
    }
    __syncthreads();
    float4 acc = make_float4(0.f, 0.f, 0.f, 0.f);
    for (int i = 0; i < cnt; i++) {
        int row = (i < n) ? toks[i] : g_perm[t0 + i];
        float4 x = *(const float4*)(v + (size_t)row * CDIM + t * 4);
        acc.x += x.x; acc.y += x.y; acc.z += x.z; acc.w += x.w;
    }
    *(float4*)(g_codv + (size_t)bk * CDIM + t * 4) = acc;
}

// ---------------- K5b: transpose cod_v -> [b][h][d][bucket] ----------------
__global__ void __launch_bounds__(256) transpose_kernel() {
    extern __shared__ float ts[];   // [256][65]
    int bh = blockIdx.x;
    int b = bh >> 4, h = bh & 15;
    int t = threadIdx.x;
    const float* src = g_codv + (size_t)b * KC * CDIM + h * D;
    #pragma unroll
    for (int i = 0; i < 16; i++) {
        int s = i * 256 + t;
        int kk = s >> 4, c4 = s & 15;
        float4 x = *(const float4*)(src + (size_t)kk * CDIM + c4 * 4);
        ts[kk * 65 + c4*4 + 0] = x.x;
        ts[kk * 65 + c4*4 + 1] = x.y;
        ts[kk * 65 + c4*4 + 2] = x.z;
        ts[kk * 65 + c4*4 + 3] = x.w;
    }
    __syncthreads();
    float* dst = g_codvt + (size_t)bh * D * KC;
    #pragma unroll
    for (int i = 0; i < 16; i++) {
        int s = i * 256 + t;
        int d = s >> 6, k4 = s & 63;
        float4 w = make_float4(ts[(k4*4+0)*65 + d], ts[(k4*4+1)*65 + d],
                               ts[(k4*4+2)*65 + d], ts[(k4*4+3)*65 + d]);
        *(float4*)(dst + (size_t)d * KC + k4 * 4) = w;
    }
}

// ---------------- K6: fp16 m16n8k16 bucketed attention ----------------
// grid(NH, B, 2), 256 threads = 8 warps, 2 CTAs/SM. K/V fp16 resident in smem.
// Each CTA handles half the q-range of its (h,b).
#define K_OFF   0
#define K_U4    (KC*4*3)                    // 3072 uint4 = 49152 B
#define V_OFF   (K_U4*16)
#define V_U4    (16*4*33)                   // 2112 uint4 = 33792 B
#define CNT_OFF (V_OFF + V_U4*16)
#define MSK_OFF (CNT_OFF + KC*4)
#define SM_TOT  (MSK_OFF + (KC/2)*4)

__global__ void __launch_bounds__(256, 2) attn_kernel(
    const float* __restrict__ q, float* __restrict__ out, int Lq)
{
    extern __shared__ char sm[];
    uint32_t* Ksm = (uint32_t*)(sm + K_OFF);
    uint32_t* Vsm = (uint32_t*)(sm + V_OFF);
    float*    cntS = (float*)(sm + CNT_OFF);
    uint32_t* mskS = (uint32_t*)(sm + MSK_OFF);

    const int t = threadIdx.x, lane = t & 31, w = t >> 5;
    const int h = blockIdx.x, b = blockIdx.y, half = blockIdx.z;
    const int j = lane & 3, g = lane >> 2;

    // ---- pack K (fp16 B-frag layout) ----
    const float2* ksrc2 = (const float2*)(g_codk + (size_t)h * KC * D);
    #pragma unroll
    for (int i = 0; i < 32; i++) {
        int s = t + 256 * i;              // 8192 float2
        int n = s >> 5, p = s & 31;
        float2 x = ksrc2[s];
        int jj = p & 3, qq = p >> 2;      // qq = 2*kc + w
        int kc = qq >> 1, ww = qq & 1;
        int slot = kc >> 1, c = ((kc & 1) << 1) | ww;
        Ksm[((n*4 + jj)*3 + slot)*4 + c] = pack_h2(x.x, x.y);
    }
    // ---- pack V^T (fp16 B-frag layout) ----
    const float2* vsrc2 = (const float2*)(g_codvt + (size_t)(b * NH + h) * D * KC);
    #pragma unroll
    for (int i = 0; i < 32; i++) {
        int s = t + 256 * i;              // 8192 float2 : d = s>>7, pair p = s&127
        int d = s >> 7, p = s & 127;
        float2 x = vsrc2[s];
        int ch = p >> 3, r = p & 7;
        int jj = r & 3, ww = r >> 2;
        int nbk = d >> 3, gg = d & 7;
        int slot = nbk >> 1, c = ((nbk & 1) << 1) | ww;
        Vsm[(((ch*4 + jj)*33) + gg*4 + slot)*4 + c] = pack_h2(x.x, x.y);
    }
    {
        float cv = (float)g_counts[b * KC + t];
        cntS[t] = cv;
    }
    __syncthreads();
    if (t < KC/2) {
        float ca = cntS[2*t], cb2 = cntS[2*t + 1];
        mskS[t] = pack_h2(ca > 0.f ? 1.f : 0.f, cb2 > 0.f ? 1.f : 0.f);
    }
    __syncthreads();

    const uint4* KB = (const uint4*)Ksm;
    const uint4* VB = (const uint4*)Vsm;
    const int qlo = half * (Lq / 2), qhi = qlo + Lq / 2;

    for (int q0 = qlo; q0 < qhi; q0 += 128) {
        // ---- Q A-fragments (scale folded, fp16) ----
        const float* qr0 = q + (size_t)(b * Lq + q0 + w * 16 + g) * CDIM + h * D;
        const float* qr8 = qr0 + 8 * CDIM;
        uint32_t qa[4][4];
        #pragma unroll
        for (int kc = 0; kc < 4; kc++) {
            float2 x0 = *(const float2*)(qr0 + kc*16 + 2*j);
            float2 x1 = *(const float2*)(qr8 + kc*16 + 2*j);
            float2 x2 = *(const float2*)(qr0 + kc*16 + 8 + 2*j);
            float2 x3 = *(const float2*)(qr8 + kc*16 + 8 + 2*j);
            qa[kc][0] = pack_h2(x0.x * 0.125f, x0.y * 0.125f);
            qa[kc][1] = pack_h2(x1.x * 0.125f, x1.y * 0.125f);
            qa[kc][2] = pack_h2(x2.x * 0.125f, x2.y * 0.125f);
            qa[kc][3] = pack_h2(x3.x * 0.125f, x3.y * 0.125f);
        }

        float O[8][4];
        #pragma unroll
        for (int nb = 0; nb < 8; nb++) {
            O[nb][0] = 0.f; O[nb][1] = 0.f; O[nb][2] = 0.f; O[nb][3] = 0.f;
        }
        float den0 = 0.f, den1 = 0.f;

        #pragma unroll 1
        for (int ch = 0; ch < 16; ch++) {
            // ---- S = Q @ K^T : buckets [ch*16, ch*16+16) ----
            int nr0 = ch * 16 + g, nr1 = nr0 + 8;
            uint4 ka0 = KB[(nr0*4 + j)*3 + 0];
            uint4 ka1 = KB[(nr0*4 + j)*3 + 1];
            uint4 kb0 = KB[(nr1*4 + j)*3 + 0];
            uint4 kb1 = KB[(nr1*4 + j)*3 + 1];
            float slo[4] = {0.f,0.f,0.f,0.f}, shi[4] = {0.f,0.f,0.f,0.f};
            mma_f16(slo, qa[0], ka0.x, ka0.y);
            mma_f16(slo, qa[1], ka0.z, ka0.w);
            mma_f16(slo, qa[2], ka1.x, ka1.y);
            mma_f16(slo, qa[3], ka1.z, ka1.w);
            mma_f16(shi, qa[0], kb0.x, kb0.y);
            mma_f16(shi, qa[1], kb0.z, kb0.w);
            mma_f16(shi, qa[2], kb1.x, kb1.y);
            mma_f16(shi, qa[3], kb1.z, kb1.w);

            // ---- e = exp(s); den += e*cnt (cnt=0 self-masks) ----
            float2 c0 = *(const float2*)(cntS + ch*16 + 2*j);
            float2 c1 = *(const float2*)(cntS + ch*16 + 8 + 2*j);
            float el0 = __expf(slo[0]), el1 = __expf(slo[1]);
            float el2 = __expf(slo[2]), el3 = __expf(slo[3]);
            float eh0 = __expf(shi[0]), eh1 = __expf(shi[1]);
            float eh2 = __expf(shi[2]), eh3 = __expf(shi[3]);
            den0 += el0*c0.x + el1*c0.y + eh0*c1.x + eh1*c1.y;
            den1 += el2*c0.x + el3*c0.y + eh2*c1.x + eh3*c1.y;

            // ---- A-frags: packed exp * 0/1 half2 mask; C-frag == A-frag ----
            uint32_t mlo = mskS[ch*8 + j], mhi = mskS[ch*8 + 4 + j];
            uint32_t A[4];
            A[0] = hmul2_u(pack_h2(el0, el1), mlo);
            A[1] = hmul2_u(pack_h2(el2, el3), mlo);
            A[2] = hmul2_u(pack_h2(eh0, eh1), mhi);
            A[3] = hmul2_u(pack_h2(eh2, eh3), mhi);

            // ---- O += P @ V ----
            const uint4* vrow = VB + (ch*4 + j)*33 + g*4;
            #pragma unroll
            for (int s = 0; s < 4; s++) {
                uint4 vv = vrow[s];
                mma_f16(O[2*s],     A, vv.x, vv.y);
                mma_f16(O[2*s + 1], A, vv.z, vv.w);
            }
        }

        // ---- reduce den across the 4 lanes of each row-quad ----
        den0 += __shfl_xor_sync(0xffffffffu, den0, 1);
        den0 += __shfl_xor_sync(0xffffffffu, den0, 2);
        den1 += __shfl_xor_sync(0xffffffffu, den1, 1);
        den1 += __shfl_xor_sync(0xffffffffu, den1, 2);
        float inv0 = 1.0f / den0;
        float inv1 = 1.0f / den1;

        // ---- epilogue ----
        float* ob0 = out + (size_t)(b * Lq + q0 + w * 16 + g) * CDIM + h * D;
        float* ob8 = ob0 + 8 * CDIM;
        #pragma unroll
        for (int nbk = 0; nbk < 8; nbk++) {
            float2 r0 = make_float2(O[nbk][0] * inv0, O[nbk][1] * inv0);
            float2 r1 = make_float2(O[nbk][2] * inv1, O[nbk][3] * inv1);
            *(float2*)(ob0 + nbk*8 + 2*j) = r0;
            *(float2*)(ob8 + nbk*8 + 2*j) = r1;
        }
    }
}

// ---------------- launch ----------------
extern "C" void kernel_launch(void* const* d_in, const int* in_sizes, int n_in,
                              void* d_out, int out_size)
{
    const float* q  = (const float*)d_in[0];
    const float* k  = (const float*)d_in[1];
    const float* v  = (const float*)d_in[2];
    const float* Wc = (const float*)d_in[3];
    const float* bc = (const float*)d_in[4];
    const float* cb = (const float*)d_in[5];

    int B    = in_sizes[6];
    int C    = in_sizes[3] / CS;
    int Lk   = in_sizes[1] / (B * C);
    int Lq   = in_sizes[0] / (B * C);
    int nTok = B * Lk;
    (void)n_in; (void)out_size;

    zero_counts_kernel<<<(B * KC + 255) / 256, 256>>>(B * KC);
    idx_kernel<<<(nTok + 63) / 64, 256>>>(k, Wc, bc, Lk, nTok);
    scan_kernel<<<1, 256>>>(B, Lk);
    scatter_kernel<<<(nTok + 255) / 256, 256>>>(Lk, nTok);
    codk_kernel<<<KC, 256>>>(cb);
    gather_kernel<<<B * KC, 256>>>(v);

    size_t tsm = 256 * 65 * sizeof(float);
    cudaFuncSetAttribute(transpose_kernel,
                         cudaFuncAttributeMaxDynamicSharedMemorySize, (int)tsm);
    transpose_kernel<<<B * NH, 256, tsm>>>();

    cudaFuncSetAttribute(attn_kernel,
                         cudaFuncAttributeMaxDynamicSharedMemorySize, SM_TOT);
    dim3 grid(NH, B, 2);
    attn_kernel<<<grid, 256, SM_TOT>>>(q, (float*)d_out, Lq);
}

// round 6
// speedup vs baseline: 3.1970x; 1.0214x over previous
#include <cuda_runtime.h>
#include <cuda_fp16.h>
#include <math.h>
#include <stdint.h>

#define CS    8
#define KC    256
#define NH    16
#define D     64
#define CDIM  1024
#define MAXB  8
#define MAXLK 4096
#define MAXTOK (MAXB*MAXLK)

// ---------------- device scratch ----------------
__device__ int   g_idx[MAXTOK];
__device__ int   g_counts[MAXB*KC];
__device__ int   g_offsets[MAXB*KC];
__device__ int   g_cursor[MAXB*KC];
__device__ int   g_perm[MAXTOK];
__device__ float g_codv[MAXB*KC*CDIM];          // [b][bucket][C]      8 MB
__device__ float g_codvt[MAXB*NH*D*KC];         // [b][h][d][bucket]   8 MB
__device__ float g_codk[NH*KC*D];               // [h][bucket][d]      1 MB

// ---------------- helpers ----------------
__device__ __forceinline__ uint32_t pack_h2(float a, float b) {
    __half2 h = __floats2half2_rn(a, b);
    return *(uint32_t*)&h;
}
__device__ __forceinline__ uint32_t hadd2_u(uint32_t a, uint32_t b) {
    __half2 r = __hadd2(*(__half2*)&a, *(__half2*)&b);
    return *(uint32_t*)&r;
}
__device__ __forceinline__ uint32_t ex2_h2(uint32_t x) {
    uint32_t r; asm("ex2.approx.f16x2 %0, %1;" : "=r"(r) : "r"(x)); return r;
}
__device__ __forceinline__ void mma_f16(float c[4], const uint32_t a[4],
                                        uint32_t b0, uint32_t b1) {
    asm volatile("mma.sync.aligned.m16n8k16.row.col.f32.f16.f16.f32 "
        "{%0,%1,%2,%3}, {%4,%5,%6,%7}, {%8,%9}, {%0,%1,%2,%3};"
        : "+f"(c[0]), "+f"(c[1]), "+f"(c[2]), "+f"(c[3])
        : "r"(a[0]), "r"(a[1]), "r"(a[2]), "r"(a[3]), "r"(b0), "r"(b1));
}

// ---------------- K0: zero counts ----------------
__global__ void zero_counts_kernel(int n) {
    int i = blockIdx.x * blockDim.x + threadIdx.x;
    if (i < n) g_counts[i] = 0;
}

// ---------------- K1: bucket index + histogram ----------------
__global__ void __launch_bounds__(256) idx_kernel(
    const float* __restrict__ k, const float* __restrict__ Wc,
    const float* __restrict__ bc, int Lk, int nTok)
{
    __shared__ float4 sW[CS * (CDIM/4)];
    __shared__ float  sbc[CS];
    int t = threadIdx.x;
    for (int i = t; i < CS * (CDIM/4); i += 256) sW[i] = ((const float4*)Wc)[i];
    if (t < CS) sbc[t] = bc[t];
    __syncthreads();

    int warp = t >> 5, lane = t & 31;
    int rowBase = (blockIdx.x * 8 + warp) * 8;
    for (int rr = 0; rr < 8; rr++) {
        int r = rowBase + rr;
        if (r >= nTok) return;
        const float4* krow = (const float4*)(k + (size_t)r * CDIM);
        float acc[CS];
        #pragma unroll
        for (int j = 0; j < CS; j++) acc[j] = 0.f;
        for (int i = lane; i < CDIM/4; i += 32) {
            float4 kv = krow[i];
            #pragma unroll
            for (int j = 0; j < CS; j++) {
                float4 w = sW[j * (CDIM/4) + i];
                acc[j] += kv.x*w.x + kv.y*w.y + kv.z*w.z + kv.w*w.w;
            }
        }
        #pragma unroll
        for (int j = 0; j < CS; j++) {
            #pragma unroll
            for (int o = 16; o >= 1; o >>= 1)
                acc[j] += __shfl_xor_sync(0xffffffffu, acc[j], o);
        }
        if (lane == 0) {
            int code = 0;
            #pragma unroll
            for (int j = 0; j < CS; j++)
                if (acc[j] + sbc[j] >= 0.f) code |= (1 << (7 - j));
            g_idx[r] = code;
            int b = r / Lk;
            atomicAdd(&g_counts[b * KC + code], 1);
        }
    }
}

// ---------------- K2: per-batch scan ----------------
__global__ void scan_kernel(int B, int Lk) {
    __shared__ int s[KC];
    int t = threadIdx.x;
    for (int b = 0; b < B; b++) {
        int v = g_counts[b * KC + t];
        s[t] = v;
        __syncthreads();
        for (int o = 1; o < KC; o <<= 1) {
            int x = (t >= o) ? s[t - o] : 0;
            __syncthreads();
            s[t] += x;
            __syncthreads();
        }
        int off = b * Lk + (s[t] - v);
        g_offsets[b * KC + t] = off;
        g_cursor[b * KC + t]  = off;
        __syncthreads();
    }
}

// ---------------- K3: scatter ----------------
__global__ void scatter_kernel(int Lk, int nTok) {
    int r = blockIdx.x * blockDim.x + threadIdx.x;
    if (r >= nTok) return;
    int b = r / Lk;
    int code = g_idx[r];
    int pos = atomicAdd(&g_cursor[b * KC + code], 1);
    g_perm[pos] = r;
}

// ---------------- K4: codebook keys, head-major [h][bucket][d] ----------------
__global__ void codk_kernel(const float* __restrict__ cb) {
    int c = blockIdx.x, t = threadIdx.x;
    float4 acc = make_float4(0.f, 0.f, 0.f, 0.f);
    #pragma unroll
    for (int j = 0; j < CS; j++) {
        int sel = ((c >> (7 - j)) & 1) ? j : (CS + j);
        float4 w = ((const float4*)cb)[sel * (CDIM/4) + t];
        acc.x += w.x; acc.y += w.y; acc.z += w.z; acc.w += w.w;
    }
    ((float4*)g_codk)[((t >> 4) * KC + c) * (D/4) + (t & 15)] = acc;
}

// ---------------- K5: gather-sum v per bucket ----------------
__global__ void __launch_bounds__(256) gather_kernel(const float* __restrict__ v) {
    int bk = blockIdx.x;
    int t0 = g_offsets[bk];
    int cnt = g_counts[bk];
    __shared__ int toks[1024];
    int t = threadIdx.x;
    int n = min(cnt, 1024);
    for (int i = t; i < n; i += 256) toks[i] = g_perm[t0 + i];
    __syncthreads();
    if (t == 0 && n > 1) {
        for (int i = 1; i < n; i++) {
            int key = toks[i]; int j = i - 1;
            while (j >= 0 && toks[j] > key) { toks[j + 1] = toks[j]; j--; }
            toks[j + 1] = key;
        }
    }
    __syncthreads();
    float4 acc = make_float4(0.f, 0.f, 0.f, 0.f);
    for (int i = 0; i < cnt; i++) {
        int row = (i < n) ? toks[i] : g_perm[t0 + i];
        float4 x = *(const float4*)(v + (size_t)row * CDIM + t * 4);
        acc.x += x.x; acc.y += x.y; acc.z += x.z; acc.w += x.w;
    }
    *(float4*)(g_codv + (size_t)bk * CDIM + t * 4) = acc;
}

// ---------------- K5b: transpose cod_v -> [b][h][d][bucket] ----------------
__global__ void __launch_bounds__(256) transpose_kernel() {
    extern __shared__ float ts[];   // [256][65]
    int bh = blockIdx.x;
    int b = bh >> 4, h = bh & 15;
    int t = threadIdx.x;
    const float* src = g_codv + (size_t)b * KC * CDIM + h * D;
    #pragma unroll
    for (int i = 0; i < 16; i++) {
        int s = i * 256 + t;
        int kk = s >> 4, c4 = s & 15;
        float4 x = *(const float4*)(src + (size_t)kk * CDIM + c4 * 4);
        ts[kk * 65 + c4*4 + 0] = x.x;
        ts[kk * 65 + c4*4 + 1] = x.y;
        ts[kk * 65 + c4*4 + 2] = x.z;
        ts[kk * 65 + c4*4 + 3] = x.w;
    }
    __syncthreads();
    float* dst = g_codvt + (size_t)bh * D * KC;
    #pragma unroll
    for (int i = 0; i < 16; i++) {
        int s = i * 256 + t;
        int d = s >> 6, k4 = s & 63;
        float4 w = make_float4(ts[(k4*4+0)*65 + d], ts[(k4*4+1)*65 + d],
                               ts[(k4*4+2)*65 + d], ts[(k4*4+3)*65 + d]);
        *(float4*)(dst + (size_t)d * KC + k4 * 4) = w;
    }
}

// ---------------- K6: fp16 m16n8k16 bucketed attention ----------------
// grid(NH, B, 2), 256 threads = 8 warps, 2 CTAs/SM. K/V fp16 resident in smem.
// Scores arrive in log2 domain (log2e folded into Q); masking is additive -inf
// before ex2.approx.f16x2; den computed by the PV MMA via a counts column (col 64).
//
// Vsm row stride 42 uint4: slots 0..3 = dims (nbk<8), slot 4 = counts column
// (dim col 64 at g=0, zeros for g>0). Phase-conflict-free: 42j+5g+s mod 8 distinct.
#define K_OFF   0
#define K_U4    (KC*4*3)                    // 3072 uint4 = 49152 B
#define V_OFF   (K_U4*16)
#define V_U4    (64*42)                     // 2688 uint4 = 43008 B
#define CNT_OFF (V_OFF + V_U4*16)
#define MSK_OFF (CNT_OFF + KC*4)
#define SM_TOT  (MSK_OFF + (KC/2)*4)

__global__ void __launch_bounds__(256, 2) attn_kernel(
    const float* __restrict__ q, float* __restrict__ out, int Lq)
{
    extern __shared__ char sm[];
    uint32_t* Ksm = (uint32_t*)(sm + K_OFF);
    uint32_t* Vsm = (uint32_t*)(sm + V_OFF);
    float*    cntS = (float*)(sm + CNT_OFF);
    uint32_t* mskS = (uint32_t*)(sm + MSK_OFF);

    const int t = threadIdx.x, lane = t & 31, w = t >> 5;
    const int h = blockIdx.x, b = blockIdx.y, half = blockIdx.z;
    const int j = lane & 3, g = lane >> 2;

    // ---- pack K (fp16 B-frag layout) ----
    const float2* ksrc2 = (const float2*)(g_codk + (size_t)h * KC * D);
    #pragma unroll
    for (int i = 0; i < 32; i++) {
        int s = t + 256 * i;              // 8192 float2
        int n = s >> 5, p = s & 31;
        float2 x = ksrc2[s];
        int jj = p & 3, qq = p >> 2;      // qq = 2*kc + w
        int kc = qq >> 1, ww = qq & 1;
        int slot = kc >> 1, c = ((kc & 1) << 1) | ww;
        Ksm[((n*4 + jj)*3 + slot)*4 + c] = pack_h2(x.x, x.y);
    }
    // ---- pack V^T (fp16 B-frag layout, slots 0..3) ----
    const float2* vsrc2 = (const float2*)(g_codvt + (size_t)(b * NH + h) * D * KC);
    #pragma unroll
    for (int i = 0; i < 32; i++) {
        int s = t + 256 * i;              // 8192 float2 : d = s>>7, pair p = s&127
        int d = s >> 7, p = s & 127;
        float2 x = vsrc2[s];
        int ch = p >> 3, r = p & 7;
        int jj = r & 3, ww = r >> 2;
        int nbk = d >> 3, gg = d & 7;
        int slot = nbk >> 1, c = ((nbk & 1) << 1) | ww;
        Vsm[(((ch*4 + jj)*42) + gg*5 + slot)*4 + c] = pack_h2(x.x, x.y);
    }
    // ---- zero slot-4 (counts) entries ----
    for (int i = t; i < 64*8; i += 256) {
        int row = i >> 3, gg = i & 7;
        uint32_t* p4 = &Vsm[(row*42 + gg*5 + 4)*4];
        p4[0] = 0; p4[1] = 0; p4[2] = 0; p4[3] = 0;
    }
    cntS[t] = (float)g_counts[b * KC + t];
    __syncthreads();
    // ---- counts column (g=0) + additive -inf masks ----
    if (t < 64) {                          // t = ch*4 + j
        int ch = t >> 2, jj = t & 3;
        uint32_t* p4 = &Vsm[(t*42 + 4)*4];
        p4[0] = pack_h2(cntS[ch*16 + 2*jj],     cntS[ch*16 + 2*jj + 1]);
        p4[1] = pack_h2(cntS[ch*16 + 8 + 2*jj], cntS[ch*16 + 8 + 2*jj + 1]);
    }
    if (t < KC/2) {
        uint32_t m = 0;
        if (!(cntS[2*t]     > 0.f)) m |= 0xFC00u;
        if (!(cntS[2*t + 1] > 0.f)) m |= 0xFC00u << 16;
        mskS[t] = m;
    }
    __syncthreads();

    const uint4* KB = (const uint4*)Ksm;
    const uint4* VB = (const uint4*)Vsm;
    const int qlo = half * (Lq / 2), qhi = qlo + Lq / 2;
    const float QS = 0.125f * 1.4426950408889634f;   // scale * log2(e)

    for (int q0 = qlo; q0 < qhi; q0 += 128) {
        // ---- Q A-fragments (scale*log2e folded, fp16) ----
        const float* qr0 = q + (size_t)(b * Lq + q0 + w * 16 + g) * CDIM + h * D;
        const float* qr8 = qr0 + 8 * CDIM;
        uint32_t qa[4][4];
        #pragma unroll
        for (int kc = 0; kc < 4; kc++) {
            float2 x0 = *(const float2*)(qr0 + kc*16 + 2*j);
            float2 x1 = *(const float2*)(qr8 + kc*16 + 2*j);
            float2 x2 = *(const float2*)(qr0 + kc*16 + 8 + 2*j);
            float2 x3 = *(const float2*)(qr8 + kc*16 + 8 + 2*j);
            qa[kc][0] = pack_h2(x0.x * QS, x0.y * QS);
            qa[kc][1] = pack_h2(x1.x * QS, x1.y * QS);
            qa[kc][2] = pack_h2(x2.x * QS, x2.y * QS);
            qa[kc][3] = pack_h2(x3.x * QS, x3.y * QS);
        }

        float O[8][4];
        #pragma unroll
        for (int nb = 0; nb < 8; nb++) {
            O[nb][0] = 0.f; O[nb][1] = 0.f; O[nb][2] = 0.f; O[nb][3] = 0.f;
        }
        float O8[4] = {0.f, 0.f, 0.f, 0.f};   // counts column -> den at col 64

        #pragma unroll 1
        for (int ch = 0; ch < 16; ch++) {
            // ---- S(log2) = Qs @ K^T : buckets [ch*16, ch*16+16) ----
            int nr0 = ch * 16 + g, nr1 = nr0 + 8;
            uint4 ka0 = KB[(nr0*4 + j)*3 + 0];
            uint4 ka1 = KB[(nr0*4 + j)*3 + 1];
            uint4 kb0 = KB[(nr1*4 + j)*3 + 0];
            uint4 kb1 = KB[(nr1*4 + j)*3 + 1];
            float slo[4] = {0.f,0.f,0.f,0.f}, shi[4] = {0.f,0.f,0.f,0.f};
            mma_f16(slo, qa[0], ka0.x, ka0.y);
            mma_f16(slo, qa[1], ka0.z, ka0.w);
            mma_f16(slo, qa[2], ka1.x, ka1.y);
            mma_f16(slo, qa[3], ka1.z, ka1.w);
            mma_f16(shi, qa[0], kb0.x, kb0.y);
            mma_f16(shi, qa[1], kb0.z, kb0.w);
            mma_f16(shi, qa[2], kb1.x, kb1.y);
            mma_f16(shi, qa[3], kb1.z, kb1.w);

            // ---- P = 2^(s + bias) packed half2 (bias = 0 or -inf) ----
            uint32_t mlo = mskS[ch*8 + j], mhi = mskS[ch*8 + 4 + j];
            uint32_t A[4];
            A[0] = ex2_h2(hadd2_u(pack_h2(slo[0], slo[1]), mlo));
            A[1] = ex2_h2(hadd2_u(pack_h2(slo[2], slo[3]), mlo));
            A[2] = ex2_h2(hadd2_u(pack_h2(shi[0], shi[1]), mhi));
            A[3] = ex2_h2(hadd2_u(pack_h2(shi[2], shi[3]), mhi));

            // ---- O += P @ V  (slot 4 = counts column -> den) ----
            const uint4* vrow = VB + (ch*4 + j)*42 + g*5;
            #pragma unroll
            for (int s = 0; s < 4; s++) {
                uint4 vv = vrow[s];
                mma_f16(O[2*s],     A, vv.x, vv.y);
                mma_f16(O[2*s + 1], A, vv.z, vv.w);
            }
            uint4 vc = vrow[4];
            mma_f16(O8, A, vc.x, vc.y);
        }

        // ---- den lives at col 64 -> c0/c2 of j=0 lanes; broadcast in quad ----
        int src = lane & 28;
        float den0 = __shfl_sync(0xffffffffu, O8[0], src);
        float den1 = __shfl_sync(0xffffffffu, O8[2], src);
        float inv0 = 1.0f / den0;
        float inv1 = 1.0f / den1;

        // ---- epilogue ----
        float* ob0 = out + (size_t)(b * Lq + q0 + w * 16 + g) * CDIM + h * D;
        float* ob8 = ob0 + 8 * CDIM;
        #pragma unroll
        for (int nbk = 0; nbk < 8; nbk++) {
            float2 r0 = make_float2(O[nbk][0] * inv0, O[nbk][1] * inv0);
            float2 r1 = make_float2(O[nbk][2] * inv1, O[nbk][3] * inv1);
            *(float2*)(ob0 + nbk*8 + 2*j) = r0;
            *(float2*)(ob8 + nbk*8 + 2*j) = r1;
        }
    }
}

// ---------------- launch ----------------
extern "C" void kernel_launch(void* const* d_in, const int* in_sizes, int n_in,
                              void* d_out, int out_size)
{
    const float* q  = (const float*)d_in[0];
    const float* k  = (const float*)d_in[1];
    const float* v  = (const float*)d_in[2];
    const float* Wc = (const float*)d_in[3];
    const float* bc = (const float*)d_in[4];
    const float* cb = (const float*)d_in[5];

    int B    = in_sizes[6];
    int C    = in_sizes[3] / CS;
    int Lk   = in_sizes[1] / (B * C);
    int Lq   = in_sizes[0] / (B * C);
    int nTok = B * Lk;
    (void)n_in; (void)out_size;

    zero_counts_kernel<<<(B * KC + 255) / 256, 256>>>(B * KC);
    idx_kernel<<<(nTok + 63) / 64, 256>>>(k, Wc, bc, Lk, nTok);
    scan_kernel<<<1, 256>>>(B, Lk);
    scatter_kernel<<<(nTok + 255) / 256, 256>>>(Lk, nTok);
    codk_kernel<<<KC, 256>>>(cb);
    gather_kernel<<<B * KC, 256>>>(v);

    size_t tsm = 256 * 65 * sizeof(float);
    cudaFuncSetAttribute(transpose_kernel,
                         cudaFuncAttributeMaxDynamicSharedMemorySize, (int)tsm);
    transpose_kernel<<<B * NH, 256, tsm>>>();

    cudaFuncSetAttribute(attn_kernel,
                         cudaFuncAttributeMaxDynamicSharedMemorySize, SM_TOT);
    dim3 grid(NH, B, 2);
    attn_kernel<<<grid, 256, SM_TOT>>>(q, (float*)d_out, Lq);
}

// round 7
// speedup vs baseline: 3.5743x; 1.1180x over previous
#include <cuda_runtime.h>
#include <cuda_fp16.h>
#include <math.h>
#include <stdint.h>

#define CS    8
#define KC    256
#define NH    16
#define D     64
#define CDIM  1024
#define MAXB  8
#define MAXLK 4096
#define MAXTOK (MAXB*MAXLK)

// ---------------- device scratch ----------------
__device__ int   g_idx[MAXTOK];
__device__ int   g_counts[MAXB*KC];
__device__ int   g_offsets[MAXB*KC];
__device__ int   g_cursor[MAXB*KC];
__device__ int   g_perm[MAXTOK];
__device__ float g_codv[MAXB*KC*CDIM];          // [b][bucket][C]      8 MB
__device__ float g_codk[NH*KC*D];               // [h][bucket][d]      1 MB

// ---------------- helpers ----------------
__device__ __forceinline__ uint32_t pack_h2(float a, float b) {
    __half2 h = __floats2half2_rn(a, b);
    return *(uint32_t*)&h;
}
__device__ __forceinline__ uint32_t hadd2_u(uint32_t a, uint32_t b) {
    __half2 r = __hadd2(*(__half2*)&a, *(__half2*)&b);
    return *(uint32_t*)&r;
}
__device__ __forceinline__ uint32_t ex2_h2(uint32_t x) {
    uint32_t r; asm("ex2.approx.f16x2 %0, %1;" : "=r"(r) : "r"(x)); return r;
}
__device__ __forceinline__ void mma_f16(float c[4], const uint32_t a[4],
                                        uint32_t b0, uint32_t b1) {
    asm volatile("mma.sync.aligned.m16n8k16.row.col.f32.f16.f16.f32 "
        "{%0,%1,%2,%3}, {%4,%5,%6,%7}, {%8,%9}, {%0,%1,%2,%3};"
        : "+f"(c[0]), "+f"(c[1]), "+f"(c[2]), "+f"(c[3])
        : "r"(a[0]), "r"(a[1]), "r"(a[2]), "r"(a[3]), "r"(b0), "r"(b1));
}

// ---------------- K0: zero counts ----------------
__global__ void zero_counts_kernel(int n) {
    int i = blockIdx.x * blockDim.x + threadIdx.x;
    if (i < n) g_counts[i] = 0;
}

// ---------------- K1: bucket index + histogram (W hoisted, 8 rows/iter) ----------------
__global__ void __launch_bounds__(256) idx_kernel(
    const float* __restrict__ k, const float* __restrict__ Wc,
    const float* __restrict__ bc, int Lk, int nTok)
{
    __shared__ float4 sW[CS * (CDIM/4)];   // 32 KB
    __shared__ float  sbc[CS];
    int t = threadIdx.x;
    for (int i = t; i < CS * (CDIM/4); i += 256) sW[i] = ((const float4*)Wc)[i];
    if (t < CS) sbc[t] = bc[t];
    __syncthreads();

    int warp = t >> 5, lane = t & 31;
    int rowBase = (blockIdx.x * 8 + warp) * 8;
    if (rowBase >= nTok) return;
    const float4* kbase = (const float4*)(k + (size_t)rowBase * CDIM);

    float acc[8][8];
    #pragma unroll
    for (int r = 0; r < 8; r++)
        #pragma unroll
        for (int j = 0; j < CS; j++) acc[r][j] = 0.f;

    for (int i = lane; i < CDIM/4; i += 32) {
        float4 wv[8];
        #pragma unroll
        for (int j = 0; j < CS; j++) wv[j] = sW[j * (CDIM/4) + i];
        #pragma unroll
        for (int r = 0; r < 8; r++) {
            float4 kv = kbase[(size_t)r * (CDIM/4) + i];
            #pragma unroll
            for (int j = 0; j < CS; j++)
                acc[r][j] += kv.x*wv[j].x + kv.y*wv[j].y + kv.z*wv[j].z + kv.w*wv[j].w;
        }
    }
    #pragma unroll
    for (int r = 0; r < 8; r++) {
        #pragma unroll
        for (int j = 0; j < CS; j++) {
            #pragma unroll
            for (int o = 16; o >= 1; o >>= 1)
                acc[r][j] += __shfl_xor_sync(0xffffffffu, acc[r][j], o);
        }
        if (lane == 0) {
            int rr = rowBase + r;
            int code = 0;
            #pragma unroll
            for (int j = 0; j < CS; j++)
                if (acc[r][j] + sbc[j] >= 0.f) code |= (1 << (7 - j));
            g_idx[rr] = code;
            int b = rr / Lk;
            atomicAdd(&g_counts[b * KC + code], 1);
        }
    }
}

// ---------------- K2: per-batch scan ----------------
__global__ void scan_kernel(int B, int Lk) {
    __shared__ int s[KC];
    int t = threadIdx.x;
    for (int b = 0; b < B; b++) {
        int v = g_counts[b * KC + t];
        s[t] = v;
        __syncthreads();
        for (int o = 1; o < KC; o <<= 1) {
            int x = (t >= o) ? s[t - o] : 0;
            __syncthreads();
            s[t] += x;
            __syncthreads();
        }
        int off = b * Lk + (s[t] - v);
        g_offsets[b * KC + t] = off;
        g_cursor[b * KC + t]  = off;
        __syncthreads();
    }
}

// ---------------- K3: scatter ----------------
__global__ void scatter_kernel(int Lk, int nTok) {
    int r = blockIdx.x * blockDim.x + threadIdx.x;
    if (r >= nTok) return;
    int b = r / Lk;
    int code = g_idx[r];
    int pos = atomicAdd(&g_cursor[b * KC + code], 1);
    g_perm[pos] = r;
}

// ---------------- K4: codebook keys, head-major [h][bucket][d] ----------------
__global__ void codk_kernel(const float* __restrict__ cb) {
    int c = blockIdx.x, t = threadIdx.x;
    float4 acc = make_float4(0.f, 0.f, 0.f, 0.f);
    #pragma unroll
    for (int j = 0; j < CS; j++) {
        int sel = ((c >> (7 - j)) & 1) ? j : (CS + j);
        float4 w = ((const float4*)cb)[sel * (CDIM/4) + t];
        acc.x += w.x; acc.y += w.y; acc.z += w.z; acc.w += w.w;
    }
    ((float4*)g_codk)[((t >> 4) * KC + c) * (D/4) + (t & 15)] = acc;
}

// ---------------- K5: gather-sum v per bucket ----------------
__global__ void __launch_bounds__(256) gather_kernel(const float* __restrict__ v) {
    int bk = blockIdx.x;
    int t0 = g_offsets[bk];
    int cnt = g_counts[bk];
    __shared__ int toks[1024];
    int t = threadIdx.x;
    int n = min(cnt, 1024);
    for (int i = t; i < n; i += 256) toks[i] = g_perm[t0 + i];
    __syncthreads();
    if (t == 0 && n > 1) {
        for (int i = 1; i < n; i++) {
            int key = toks[i]; int j = i - 1;
            while (j >= 0 && toks[j] > key) { toks[j + 1] = toks[j]; j--; }
            toks[j + 1] = key;
        }
    }
    __syncthreads();
    float4 acc = make_float4(0.f, 0.f, 0.f, 0.f);
    for (int i = 0; i < cnt; i++) {
        int row = (i < n) ? toks[i] : g_perm[t0 + i];
        float4 x = *(const float4*)(v + (size_t)row * CDIM + t * 4);
        acc.x += x.x; acc.y += x.y; acc.z += x.z; acc.w += x.w;
    }
    *(float4*)(g_codv + (size_t)bk * CDIM + t * 4) = acc;
}

// ---------------- K6: fp16 m16n8k16 bucketed attention, M=32/warp ----------------
// grid(NH, B), 256 threads = 8 warps, 1 CTA/SM (~156KB smem). Each warp owns
// 32 q-rows (two m16 blocks sharing K/V fragments -> half the LDS per row).
// Scores in log2 domain; additive -inf mask; den via counts column (col 64).
#define K_OFF   0
#define V_OFF   49152
#define CNT_OFF 92160
#define MSK_OFF 93184
#define VST_OFF 93696
#define SM_TOT  (VST_OFF + KC*D*4)          // + 64KB staging = 159232

__global__ void __launch_bounds__(256, 1) attn_kernel(
    const float* __restrict__ q, float* __restrict__ out, int Lq)
{
    extern __shared__ char sm[];
    uint32_t* Ksm = (uint32_t*)(sm + K_OFF);
    uint32_t* Vsm = (uint32_t*)(sm + V_OFF);
    float*    cntS = (float*)(sm + CNT_OFF);
    uint32_t* mskS = (uint32_t*)(sm + MSK_OFF);
    float*    Vst  = (float*)(sm + VST_OFF);

    const int t = threadIdx.x, lane = t & 31, w = t >> 5;
    const int h = blockIdx.x, b = blockIdx.y;
    const int j = lane & 3, g = lane >> 2;

    // ---- Phase A: pack K, zero slot-4, stage V slice, load counts ----
    const float2* ksrc2 = (const float2*)(g_codk + (size_t)h * KC * D);
    #pragma unroll
    for (int i = 0; i < 32; i++) {
        int s = t + 256 * i;              // 8192 float2
        int n = s >> 5, p = s & 31;
        float2 x = ksrc2[s];
        int jj = p & 3, qq = p >> 2;
        int kc = qq >> 1, ww = qq & 1;
        int slot = kc >> 1, c = ((kc & 1) << 1) | ww;
        Ksm[((n*4 + jj)*3 + slot)*4 + c] = pack_h2(x.x, x.y);
    }
    for (int i = t; i < 64*8; i += 256) {
        int row = i >> 3, gg = i & 7;
        uint32_t* p4 = &Vsm[(row*42 + gg*5 + 4)*4];
        p4[0] = 0; p4[1] = 0; p4[2] = 0; p4[3] = 0;
    }
    {   // stage cod_v (b,h) slice: [256 buckets][64 dims]
        const float4* vsrc = (const float4*)(g_codv + ((size_t)b * KC) * CDIM + h * D);
        float4* vst4 = (float4*)Vst;
        #pragma unroll
        for (int i = 0; i < 16; i++) {
            int s = t + 256 * i;          // 4096 float4
            int n = s >> 4, c4 = s & 15;
            vst4[n * 16 + c4] = vsrc[(size_t)n * (CDIM/4) + c4];
        }
    }
    cntS[t] = (float)g_counts[b * KC + t];
    __syncthreads();

    // ---- Phase B: pack V^T frags from staging, counts column, masks ----
    #pragma unroll
    for (int i = 0; i < 32; i++) {
        int s = t + 256 * i;              // 8192 (d, bucket-pair) elements
        int d = s & 63, p = s >> 6;
        float x0 = Vst[(2*p)     * 64 + d];
        float x1 = Vst[(2*p + 1) * 64 + d];
        int ch = p >> 3, r = p & 7;
        int jj = r & 3, ww = r >> 2;
        int nbk = d >> 3, gg = d & 7;
        int slot = nbk >> 1, c = ((nbk & 1) << 1) | ww;
        Vsm[(((ch*4 + jj)*42) + gg*5 + slot)*4 + c] = pack_h2(x0, x1);
    }
    if (t < 64) {                          // counts column at dim col 64 (g=0)
        int ch = t >> 2, jj = t & 3;
        uint32_t* p4 = &Vsm[(t*42 + 4)*4];
        p4[0] = pack_h2(cntS[ch*16 + 2*jj],     cntS[ch*16 + 2*jj + 1]);
        p4[1] = pack_h2(cntS[ch*16 + 8 + 2*jj], cntS[ch*16 + 8 + 2*jj + 1]);
    }
    if (t < KC/2) {
        uint32_t m = 0;
        if (!(cntS[2*t]     > 0.f)) m |= 0xFC00u;
        if (!(cntS[2*t + 1] > 0.f)) m |= 0xFC00u << 16;
        mskS[t] = m;
    }
    __syncthreads();

    const uint4* KB = (const uint4*)Ksm;
    const uint4* VB = (const uint4*)Vsm;
    const float QS = 0.125f * 1.4426950408889634f;   // scale * log2(e)

    for (int q0 = 0; q0 < Lq; q0 += 256) {
        // ---- Q A-fragments for two m16 blocks (rows w*32+[0,16) and +[16,32)) ----
        const float* qr0  = q + (size_t)(b * Lq + q0 + w * 32 + g) * CDIM + h * D;
        const float* qr8  = qr0 + 8  * CDIM;
        const float* qr16 = qr0 + 16 * CDIM;
        const float* qr24 = qr0 + 24 * CDIM;
        uint32_t qa0[4][4], qa1[4][4];
        #pragma unroll
        for (int kc = 0; kc < 4; kc++) {
            float2 x0 = *(const float2*)(qr0  + kc*16 + 2*j);
            float2 x1 = *(const float2*)(qr8  + kc*16 + 2*j);
            float2 x2 = *(const float2*)(qr0  + kc*16 + 8 + 2*j);
            float2 x3 = *(const float2*)(qr8  + kc*16 + 8 + 2*j);
            qa0[kc][0] = pack_h2(x0.x * QS, x0.y * QS);
            qa0[kc][1] = pack_h2(x1.x * QS, x1.y * QS);
            qa0[kc][2] = pack_h2(x2.x * QS, x2.y * QS);
            qa0[kc][3] = pack_h2(x3.x * QS, x3.y * QS);
            float2 y0 = *(const float2*)(qr16 + kc*16 + 2*j);
            float2 y1 = *(const float2*)(qr24 + kc*16 + 2*j);
            float2 y2 = *(const float2*)(qr16 + kc*16 + 8 + 2*j);
            float2 y3 = *(const float2*)(qr24 + kc*16 + 8 + 2*j);
            qa1[kc][0] = pack_h2(y0.x * QS, y0.y * QS);
            qa1[kc][1] = pack_h2(y1.x * QS, y1.y * QS);
            qa1[kc][2] = pack_h2(y2.x * QS, y2.y * QS);
            qa1[kc][3] = pack_h2(y3.x * QS, y3.y * QS);
        }

        float O0[8][4], O1[8][4];
        #pragma unroll
        for (int nb = 0; nb < 8; nb++) {
            O0[nb][0]=0.f; O0[nb][1]=0.f; O0[nb][2]=0.f; O0[nb][3]=0.f;
            O1[nb][0]=0.f; O1[nb][1]=0.f; O1[nb][2]=0.f; O1[nb][3]=0.f;
        }
        float O8a[4] = {0.f,0.f,0.f,0.f}, O8b[4] = {0.f,0.f,0.f,0.f};

        #pragma unroll 1
        for (int ch = 0; ch < 16; ch++) {
            int nr0 = ch * 16 + g, nr1 = nr0 + 8;
            uint4 ka0 = KB[(nr0*4 + j)*3 + 0];
            uint4 ka1 = KB[(nr0*4 + j)*3 + 1];
            uint4 kb0 = KB[(nr1*4 + j)*3 + 0];
            uint4 kb1 = KB[(nr1*4 + j)*3 + 1];

            float s0lo[4] = {0.f,0.f,0.f,0.f}, s0hi[4] = {0.f,0.f,0.f,0.f};
            float s1lo[4] = {0.f,0.f,0.f,0.f}, s1hi[4] = {0.f,0.f,0.f,0.f};
            mma_f16(s0lo, qa0[0], ka0.x, ka0.y);
            mma_f16(s0lo, qa0[1], ka0.z, ka0.w);
            mma_f16(s0lo, qa0[2], ka1.x, ka1.y);
            mma_f16(s0lo, qa0[3], ka1.z, ka1.w);
            mma_f16(s0hi, qa0[0], kb0.x, kb0.y);
            mma_f16(s0hi, qa0[1], kb0.z, kb0.w);
            mma_f16(s0hi, qa0[2], kb1.x, kb1.y);
            mma_f16(s0hi, qa0[3], kb1.z, kb1.w);
            mma_f16(s1lo, qa1[0], ka0.x, ka0.y);
            mma_f16(s1lo, qa1[1], ka0.z, ka0.w);
            mma_f16(s1lo, qa1[2], ka1.x, ka1.y);
            mma_f16(s1lo, qa1[3], ka1.z, ka1.w);
            mma_f16(s1hi, qa1[0], kb0.x, kb0.y);
            mma_f16(s1hi, qa1[1], kb0.z, kb0.w);
            mma_f16(s1hi, qa1[2], kb1.x, kb1.y);
            mma_f16(s1hi, qa1[3], kb1.z, kb1.w);

            uint32_t mlo = mskS[ch*8 + j], mhi = mskS[ch*8 + 4 + j];
            uint32_t A0[4], A1[4];
            A0[0] = ex2_h2(hadd2_u(pack_h2(s0lo[0], s0lo[1]), mlo));
            A0[1] = ex2_h2(hadd2_u(pack_h2(s0lo[2], s0lo[3]), mlo));
            A0[2] = ex2_h2(hadd2_u(pack_h2(s0hi[0], s0hi[1]), mhi));
            A0[3] = ex2_h2(hadd2_u(pack_h2(s0hi[2], s0hi[3]), mhi));
            A1[0] = ex2_h2(hadd2_u(pack_h2(s1lo[0], s1lo[1]), mlo));
            A1[1] = ex2_h2(hadd2_u(pack_h2(s1lo[2], s1lo[3]), mlo));
            A1[2] = ex2_h2(hadd2_u(pack_h2(s1hi[0], s1hi[1]), mhi));
            A1[3] = ex2_h2(hadd2_u(pack_h2(s1hi[2], s1hi[3]), mhi));

            const uint4* vrow = VB + (ch*4 + j)*42 + g*5;
            #pragma unroll
            for (int s = 0; s < 4; s++) {
                uint4 vv = vrow[s];
                mma_f16(O0[2*s],     A0, vv.x, vv.y);
                mma_f16(O0[2*s + 1], A0, vv.z, vv.w);
                mma_f16(O1[2*s],     A1, vv.x, vv.y);
                mma_f16(O1[2*s + 1], A1, vv.z, vv.w);
            }
            uint4 vc = vrow[4];
            mma_f16(O8a, A0, vc.x, vc.y);
            mma_f16(O8b, A1, vc.x, vc.y);
        }

        // ---- den at col 64 (j=0 lanes), broadcast within quad ----
        int src = lane & 28;
        float d00 = __shfl_sync(0xffffffffu, O8a[0], src);
        float d01 = __shfl_sync(0xffffffffu, O8a[2], src);
        float d10 = __shfl_sync(0xffffffffu, O8b[0], src);
        float d11 = __shfl_sync(0xffffffffu, O8b[2], src);
        float i00 = 1.0f / d00, i01 = 1.0f / d01;
        float i10 = 1.0f / d10, i11 = 1.0f / d11;

        // ---- epilogue: two blocks ----
        float* ob0  = out + (size_t)(b * Lq + q0 + w * 32 + g) * CDIM + h * D;
        float* ob8  = ob0 + 8  * CDIM;
        float* ob16 = ob0 + 16 * CDIM;
        float* ob24 = ob0 + 24 * CDIM;
        #pragma unroll
        for (int nbk = 0; nbk < 8; nbk++) {
            *(float2*)(ob0  + nbk*8 + 2*j) = make_float2(O0[nbk][0]*i00, O0[nbk][1]*i00);
            *(float2*)(ob8  + nbk*8 + 2*j) = make_float2(O0[nbk][2]*i01, O0[nbk][3]*i01);
            *(float2*)(ob16 + nbk*8 + 2*j) = make_float2(O1[nbk][0]*i10, O1[nbk][1]*i10);
            *(float2*)(ob24 + nbk*8 + 2*j) = make_float2(O1[nbk][2]*i11, O1[nbk][3]*i11);
        }
    }
}

// ---------------- launch ----------------
extern "C" void kernel_launch(void* const* d_in, const int* in_sizes, int n_in,
                              void* d_out, int out_size)
{
    const float* q  = (const float*)d_in[0];
    const float* k  = (const float*)d_in[1];
    const float* v  = (const float*)d_in[2];
    const float* Wc = (const float*)d_in[3];
    const float* bc = (const float*)d_in[4];
    const float* cb = (const float*)d_in[5];

    int B    = in_sizes[6];
    int C    = in_sizes[3] / CS;
    int Lk   = in_sizes[1] / (B * C);
    int Lq   = in_sizes[0] / (B * C);
    int nTok = B * Lk;
    (void)n_in; (void)out_size;

    zero_counts_kernel<<<(B * KC + 255) / 256, 256>>>(B * KC);
    idx_kernel<<<(nTok + 63) / 64, 256>>>(k, Wc, bc, Lk, nTok);
    scan_kernel<<<1, 256>>>(B, Lk);
    scatter_kernel<<<(nTok + 255) / 256, 256>>>(Lk, nTok);
    codk_kernel<<<KC, 256>>>(cb);
    gather_kernel<<<B * KC, 256>>>(v);

    cudaFuncSetAttribute(attn_kernel,
                         cudaFuncAttributeMaxDynamicSharedMemorySize, SM_TOT);
    dim3 grid(NH, B);
    attn_kernel<<<grid, 256, SM_TOT>>>(q, (float*)d_out, Lq);
}

// round 8
// speedup vs baseline: 4.0829x; 1.1423x over previous
#include <cuda_runtime.h>
#include <cuda_fp16.h>
#include <math.h>
#include <stdint.h>

#define CS    8
#define KC    256
#define NH    16
#define D     64
#define CDIM  1024
#define MAXB  8
#define MAXLK 4096
#define MAXTOK (MAXB*MAXLK)

// ---------------- device scratch ----------------
__device__ int   g_idx[MAXTOK];
__device__ int   g_counts[MAXB*KC];
__device__ int   g_offsets[MAXB*KC];
__device__ int   g_cursor[MAXB*KC];
__device__ int   g_perm[MAXTOK];
__device__ float g_codv[MAXB*KC*CDIM];          // [b][bucket][C]  8 MB

// ---------------- helpers ----------------
__device__ __forceinline__ uint32_t pack_h2(float a, float b) {
    __half2 h = __floats2half2_rn(a, b);
    return *(uint32_t*)&h;
}
__device__ __forceinline__ uint32_t hadd2_u(uint32_t a, uint32_t b) {
    __half2 r = __hadd2(*(__half2*)&a, *(__half2*)&b);
    return *(uint32_t*)&r;
}
__device__ __forceinline__ uint32_t ex2_h2(uint32_t x) {
    uint32_t r; asm("ex2.approx.f16x2 %0, %1;" : "=r"(r) : "r"(x)); return r;
}
__device__ __forceinline__ void mma_f16(float c[4], const uint32_t a[4],
                                        uint32_t b0, uint32_t b1) {
    asm volatile("mma.sync.aligned.m16n8k16.row.col.f32.f16.f16.f32 "
        "{%0,%1,%2,%3}, {%4,%5,%6,%7}, {%8,%9}, {%0,%1,%2,%3};"
        : "+f"(c[0]), "+f"(c[1]), "+f"(c[2]), "+f"(c[3])
        : "r"(a[0]), "r"(a[1]), "r"(a[2]), "r"(a[3]), "r"(b0), "r"(b1));
}

// ---------------- K0: zero counts ----------------
__global__ void zero_counts_kernel(int n) {
    int i = blockIdx.x * blockDim.x + threadIdx.x;
    if (i < n) g_counts[i] = 0;
}

// ---------------- K1: bucket index + histogram (W hoisted, 8 rows/iter) ----------------
__global__ void __launch_bounds__(256) idx_kernel(
    const float* __restrict__ k, const float* __restrict__ Wc,
    const float* __restrict__ bc, int Lk, int nTok)
{
    __shared__ float4 sW[CS * (CDIM/4)];   // 32 KB
    __shared__ float  sbc[CS];
    int t = threadIdx.x;
    for (int i = t; i < CS * (CDIM/4); i += 256) sW[i] = ((const float4*)Wc)[i];
    if (t < CS) sbc[t] = bc[t];
    __syncthreads();

    int warp = t >> 5, lane = t & 31;
    int rowBase = (blockIdx.x * 8 + warp) * 8;
    if (rowBase >= nTok) return;
    const float4* kbase = (const float4*)(k + (size_t)rowBase * CDIM);

    float acc[8][8];
    #pragma unroll
    for (int r = 0; r < 8; r++)
        #pragma unroll
        for (int j = 0; j < CS; j++) acc[r][j] = 0.f;

    for (int i = lane; i < CDIM/4; i += 32) {
        float4 wv[8];
        #pragma unroll
        for (int j = 0; j < CS; j++) wv[j] = sW[j * (CDIM/4) + i];
        #pragma unroll
        for (int r = 0; r < 8; r++) {
            float4 kv = kbase[(size_t)r * (CDIM/4) + i];
            #pragma unroll
            for (int j = 0; j < CS; j++)
                acc[r][j] += kv.x*wv[j].x + kv.y*wv[j].y + kv.z*wv[j].z + kv.w*wv[j].w;
        }
    }
    #pragma unroll
    for (int r = 0; r < 8; r++) {
        #pragma unroll
        for (int j = 0; j < CS; j++) {
            #pragma unroll
            for (int o = 16; o >= 1; o >>= 1)
                acc[r][j] += __shfl_xor_sync(0xffffffffu, acc[r][j], o);
        }
        if (lane == 0) {
            int rr = rowBase + r;
            int code = 0;
            #pragma unroll
            for (int j = 0; j < CS; j++)
                if (acc[r][j] + sbc[j] >= 0.f) code |= (1 << (7 - j));
            g_idx[rr] = code;
            int b = rr / Lk;
            atomicAdd(&g_counts[b * KC + code], 1);
        }
    }
}

// ---------------- K2: per-batch scan (one block per batch) ----------------
__global__ void scan_kernel(int Lk) {
    __shared__ int s[KC];
    int t = threadIdx.x, b = blockIdx.x;
    int v = g_counts[b * KC + t];
    s[t] = v;
    __syncthreads();
    for (int o = 1; o < KC; o <<= 1) {
        int x = (t >= o) ? s[t - o] : 0;
        __syncthreads();
        s[t] += x;
        __syncthreads();
    }
    int off = b * Lk + (s[t] - v);
    g_offsets[b * KC + t] = off;
    g_cursor[b * KC + t]  = off;
}

// ---------------- K3: scatter ----------------
__global__ void scatter_kernel(int Lk, int nTok) {
    int r = blockIdx.x * blockDim.x + threadIdx.x;
    if (r >= nTok) return;
    int b = r / Lk;
    int code = g_idx[r];
    int pos = atomicAdd(&g_cursor[b * KC + code], 1);
    g_perm[pos] = r;
}

// ---------------- K5: gather-sum v per bucket ----------------
__global__ void __launch_bounds__(256) gather_kernel(const float* __restrict__ v) {
    int bk = blockIdx.x;
    int t0 = g_offsets[bk];
    int cnt = g_counts[bk];
    __shared__ int toks[1024];
    int t = threadIdx.x;
    int n = min(cnt, 1024);
    for (int i = t; i < n; i += 256) toks[i] = g_perm[t0 + i];
    __syncthreads();
    if (t == 0 && n > 1) {
        for (int i = 1; i < n; i++) {
            int key = toks[i]; int j = i - 1;
            while (j >= 0 && toks[j] > key) { toks[j + 1] = toks[j]; j--; }
            toks[j + 1] = key;
        }
    }
    __syncthreads();
    float4 acc = make_float4(0.f, 0.f, 0.f, 0.f);
    for (int i = 0; i < cnt; i++) {
        int row = (i < n) ? toks[i] : g_perm[t0 + i];
        float4 x = *(const float4*)(v + (size_t)row * CDIM + t * 4);
        acc.x += x.x; acc.y += x.y; acc.z += x.z; acc.w += x.w;
    }
    *(float4*)(g_codv + (size_t)bk * CDIM + t * 4) = acc;
}

// ---------------- K6: low-rank fp16 bucketed attention, M=32/warp ----------------
// S = (Q·cbT)·baseT : T[rows,16] via cb frags, then S via 0/1 base frags.
// grid(NH, B), 256 threads = 8 warps, 1 CTA/SM (~121KB smem).
// Scores in log2 domain (log2e*scale folded into cb); additive -inf mask;
// den via counts column (dim col 64 of V).
#define CB_OFF  0
#define BA_OFF  3072
#define V_OFF   11264
#define CNT_OFF 54272
#define MSK_OFF 55296
#define VST_OFF 55808
#define SM_TOT  (VST_OFF + KC*D*4)     // 121344

__global__ void __launch_bounds__(256, 1) attn_kernel(
    const float* __restrict__ q, const float* __restrict__ cb,
    float* __restrict__ out, int Lq)
{
    extern __shared__ char sm[];
    uint32_t* Cbs  = (uint32_t*)(sm + CB_OFF);
    uint2*    BA2  = (uint2*)   (sm + BA_OFF);
    uint32_t* Vsm  = (uint32_t*)(sm + V_OFF);
    float*    cntS = (float*)   (sm + CNT_OFF);
    uint32_t* mskS = (uint32_t*)(sm + MSK_OFF);
    float*    Vst  = (float*)   (sm + VST_OFF);

    const int t = threadIdx.x, lane = t & 31, w = t >> 5;
    const int h = blockIdx.x, b = blockIdx.y;
    const int j = lane & 3, g = lane >> 2;
    const float QS = 0.125f * 1.4426950408889634f;   // scale * log2(e)

    // ---- Phase A: pack cb frags (QS folded), base frags, zero V slot-4,
    //      stage cod_v slice, counts ----
    #pragma unroll
    for (int i = 0; i < 2; i++) {
        int s = t + 256 * i;              // 512 float2 : n = j-coef row, p = dim pair
        int n = s >> 5, p = s & 31;
        const float* src = cb + (size_t)n * CDIM + h * D + 2 * (p);
        float2 x = make_float2(src[0] * QS, src[1] * QS);
        int jj = p & 3, qq = p >> 2;
        int kc = qq >> 1, ww = qq & 1;
        int slot = kc >> 1, c = ((kc & 1) << 1) | ww;
        Cbs[((n*4 + jj)*3 + slot)*4 + c] = pack_h2(x.x, x.y);
    }
    #pragma unroll
    for (int i = 0; i < 4; i++) {
        int s = t + 256 * i;              // 1024 : bucket n, jj
        int n = s >> 2, jj = s & 3;
        float b0a = (float)((n >> (7 - 2*jj)) & 1);
        float b0b = (float)((n >> (7 - (2*jj+1))) & 1);
        BA2[n*4 + jj] = make_uint2(pack_h2(b0a, b0b),
                                   pack_h2(1.f - b0a, 1.f - b0b));
    }
    for (int i = t; i < 64*8; i += 256) {
        int row = i >> 3, gg = i & 7;
        uint32_t* p4 = &Vsm[(row*42 + gg*5 + 4)*4];
        p4[0] = 0; p4[1] = 0; p4[2] = 0; p4[3] = 0;
    }
    {   // stage cod_v (b,h) slice: [256 buckets][64 dims]
        const float4* vsrc = (const float4*)(g_codv + ((size_t)b * KC) * CDIM + h * D);
        float4* vst4 = (float4*)Vst;
        #pragma unroll
        for (int i = 0; i < 16; i++) {
            int s = t + 256 * i;
            int n = s >> 4, c4 = s & 15;
            vst4[n * 16 + c4] = vsrc[(size_t)n * (CDIM/4) + c4];
        }
    }
    cntS[t] = (float)g_counts[b * KC + t];
    __syncthreads();

    // ---- Phase B: pack V^T frags from staging, counts column, masks ----
    #pragma unroll
    for (int i = 0; i < 32; i++) {
        int s = t + 256 * i;
        int d = s & 63, p = s >> 6;
        float x0 = Vst[(2*p)     * 64 + d];
        float x1 = Vst[(2*p + 1) * 64 + d];
        int ch = p >> 3, r = p & 7;
        int jj = r & 3, ww = r >> 2;
        int nbk = d >> 3, gg = d & 7;
        int slot = nbk >> 1, c = ((nbk & 1) << 1) | ww;
        Vsm[(((ch*4 + jj)*42) + gg*5 + slot)*4 + c] = pack_h2(x0, x1);
    }
    if (t < 64) {                          // counts column at dim col 64 (g=0)
        int ch = t >> 2, jj = t & 3;
        uint32_t* p4 = &Vsm[(t*42 + 4)*4];
        p4[0] = pack_h2(cntS[ch*16 + 2*jj],     cntS[ch*16 + 2*jj + 1]);
        p4[1] = pack_h2(cntS[ch*16 + 8 + 2*jj], cntS[ch*16 + 8 + 2*jj + 1]);
    }
    if (t < KC/2) {
        uint32_t m = 0;
        if (!(cntS[2*t]     > 0.f)) m |= 0xFC00u;
        if (!(cntS[2*t + 1] > 0.f)) m |= 0xFC00u << 16;
        mskS[t] = m;
    }
    __syncthreads();

    const uint4* CB4 = (const uint4*)Cbs;
    const uint4* VB  = (const uint4*)Vsm;

    // cb B-frags for T (rows g and 8+g), loaded once
    uint4 cbA0 = CB4[(g*4 + j)*3 + 0];
    uint4 cbA1 = CB4[(g*4 + j)*3 + 1];
    uint4 cbB0 = CB4[((8+g)*4 + j)*3 + 0];
    uint4 cbB1 = CB4[((8+g)*4 + j)*3 + 1];

    for (int q0 = 0; q0 < Lq; q0 += 256) {
        // ---- T = Q @ cb^T for two m16 blocks; convert C-frag -> A-frag ----
        uint32_t AT0[4], AT1[4];
        {
            const float* qr0 = q + (size_t)(b * Lq + q0 + w * 32 + g) * CDIM + h * D;
            const float* qr8 = qr0 + 8 * CDIM;
            uint32_t qa[4][4];
            #pragma unroll
            for (int kc = 0; kc < 4; kc++) {
                float2 x0 = *(const float2*)(qr0 + kc*16 + 2*j);
                float2 x1 = *(const float2*)(qr8 + kc*16 + 2*j);
                float2 x2 = *(const float2*)(qr0 + kc*16 + 8 + 2*j);
                float2 x3 = *(const float2*)(qr8 + kc*16 + 8 + 2*j);
                qa[kc][0] = pack_h2(x0.x, x0.y);
                qa[kc][1] = pack_h2(x1.x, x1.y);
                qa[kc][2] = pack_h2(x2.x, x2.y);
                qa[kc][3] = pack_h2(x3.x, x3.y);
            }
            float Tlo[4] = {0.f,0.f,0.f,0.f}, Thi[4] = {0.f,0.f,0.f,0.f};
            mma_f16(Tlo, qa[0], cbA0.x, cbA0.y);
            mma_f16(Tlo, qa[1], cbA0.z, cbA0.w);
            mma_f16(Tlo, qa[2], cbA1.x, cbA1.y);
            mma_f16(Tlo, qa[3], cbA1.z, cbA1.w);
            mma_f16(Thi, qa[0], cbB0.x, cbB0.y);
            mma_f16(Thi, qa[1], cbB0.z, cbB0.w);
            mma_f16(Thi, qa[2], cbB1.x, cbB1.y);
            mma_f16(Thi, qa[3], cbB1.z, cbB1.w);
            AT0[0] = pack_h2(Tlo[0], Tlo[1]);
            AT0[1] = pack_h2(Tlo[2], Tlo[3]);
            AT0[2] = pack_h2(Thi[0], Thi[1]);
            AT0[3] = pack_h2(Thi[2], Thi[3]);
        }
        {
            const float* qr16 = q + (size_t)(b * Lq + q0 + w * 32 + 16 + g) * CDIM + h * D;
            const float* qr24 = qr16 + 8 * CDIM;
            uint32_t qa[4][4];
            #pragma unroll
            for (int kc = 0; kc < 4; kc++) {
                float2 x0 = *(const float2*)(qr16 + kc*16 + 2*j);
                float2 x1 = *(const float2*)(qr24 + kc*16 + 2*j);
                float2 x2 = *(const float2*)(qr16 + kc*16 + 8 + 2*j);
                float2 x3 = *(const float2*)(qr24 + kc*16 + 8 + 2*j);
                qa[kc][0] = pack_h2(x0.x, x0.y);
                qa[kc][1] = pack_h2(x1.x, x1.y);
                qa[kc][2] = pack_h2(x2.x, x2.y);
                qa[kc][3] = pack_h2(x3.x, x3.y);
            }
            float Tlo[4] = {0.f,0.f,0.f,0.f}, Thi[4] = {0.f,0.f,0.f,0.f};
            mma_f16(Tlo, qa[0], cbA0.x, cbA0.y);
            mma_f16(Tlo, qa[1], cbA0.z, cbA0.w);
            mma_f16(Tlo, qa[2], cbA1.x, cbA1.y);
            mma_f16(Tlo, qa[3], cbA1.z, cbA1.w);
            mma_f16(Thi, qa[0], cbB0.x, cbB0.y);
            mma_f16(Thi, qa[1], cbB0.z, cbB0.w);
            mma_f16(Thi, qa[2], cbB1.x, cbB1.y);
            mma_f16(Thi, qa[3], cbB1.z, cbB1.w);
            AT1[0] = pack_h2(Tlo[0], Tlo[1]);
            AT1[1] = pack_h2(Tlo[2], Tlo[3]);
            AT1[2] = pack_h2(Thi[0], Thi[1]);
            AT1[3] = pack_h2(Thi[2], Thi[3]);
        }

        float O0[8][4], O1[8][4];
        #pragma unroll
        for (int nb = 0; nb < 8; nb++) {
            O0[nb][0]=0.f; O0[nb][1]=0.f; O0[nb][2]=0.f; O0[nb][3]=0.f;
            O1[nb][0]=0.f; O1[nb][1]=0.f; O1[nb][2]=0.f; O1[nb][3]=0.f;
        }
        float O8a[4] = {0.f,0.f,0.f,0.f}, O8b[4] = {0.f,0.f,0.f,0.f};

        #pragma unroll 1
        for (int ch = 0; ch < 16; ch++) {
            // ---- S(log2) = T @ base^T : buckets [ch*16, ch*16+16) ----
            uint2 ba = BA2[(ch*16 + g)*4 + j];
            uint2 bb = BA2[(ch*16 + 8 + g)*4 + j];
            float s0lo[4] = {0.f,0.f,0.f,0.f}, s0hi[4] = {0.f,0.f,0.f,0.f};
            float s1lo[4] = {0.f,0.f,0.f,0.f}, s1hi[4] = {0.f,0.f,0.f,0.f};
            mma_f16(s0lo, AT0, ba.x, ba.y);
            mma_f16(s0hi, AT0, bb.x, bb.y);
            mma_f16(s1lo, AT1, ba.x, ba.y);
            mma_f16(s1hi, AT1, bb.x, bb.y);

            uint32_t mlo = mskS[ch*8 + j], mhi = mskS[ch*8 + 4 + j];
            uint32_t A0[4], A1[4];
            A0[0] = ex2_h2(hadd2_u(pack_h2(s0lo[0], s0lo[1]), mlo));
            A0[1] = ex2_h2(hadd2_u(pack_h2(s0lo[2], s0lo[3]), mlo));
            A0[2] = ex2_h2(hadd2_u(pack_h2(s0hi[0], s0hi[1]), mhi));
            A0[3] = ex2_h2(hadd2_u(pack_h2(s0hi[2], s0hi[3]), mhi));
            A1[0] = ex2_h2(hadd2_u(pack_h2(s1lo[0], s1lo[1]), mlo));
            A1[1] = ex2_h2(hadd2_u(pack_h2(s1lo[2], s1lo[3]), mlo));
            A1[2] = ex2_h2(hadd2_u(pack_h2(s1hi[0], s1hi[1]), mhi));
            A1[3] = ex2_h2(hadd2_u(pack_h2(s1hi[2], s1hi[3]), mhi));

            const uint4* vrow = VB + (ch*4 + j)*42 + g*5;
            #pragma unroll
            for (int s = 0; s < 4; s++) {
                uint4 vv = vrow[s];
                mma_f16(O0[2*s],     A0, vv.x, vv.y);
                mma_f16(O0[2*s + 1], A0, vv.z, vv.w);
                mma_f16(O1[2*s],     A1, vv.x, vv.y);
                mma_f16(O1[2*s + 1], A1, vv.z, vv.w);
            }
            uint4 vc = vrow[4];
            mma_f16(O8a, A0, vc.x, vc.y);
            mma_f16(O8b, A1, vc.x, vc.y);
        }

        // ---- den at col 64 (j=0 lanes), broadcast within quad ----
        int src = lane & 28;
        float d00 = __shfl_sync(0xffffffffu, O8a[0], src);
        float d01 = __shfl_sync(0xffffffffu, O8a[2], src);
        float d10 = __shfl_sync(0xffffffffu, O8b[0], src);
        float d11 = __shfl_sync(0xffffffffu, O8b[2], src);
        float i00 = 1.0f / d00, i01 = 1.0f / d01;
        float i10 = 1.0f / d10, i11 = 1.0f / d11;

        // ---- epilogue: two blocks ----
        float* ob0  = out + (size_t)(b * Lq + q0 + w * 32 + g) * CDIM + h * D;
        float* ob8  = ob0 + 8  * CDIM;
        float* ob16 = ob0 + 16 * CDIM;
        float* ob24 = ob0 + 24 * CDIM;
        #pragma unroll
        for (int nbk = 0; nbk < 8; nbk++) {
            *(float2*)(ob0  + nbk*8 + 2*j) = make_float2(O0[nbk][0]*i00, O0[nbk][1]*i00);
            *(float2*)(ob8  + nbk*8 + 2*j) = make_float2(O0[nbk][2]*i01, O0[nbk][3]*i01);
            *(float2*)(ob16 + nbk*8 + 2*j) = make_float2(O1[nbk][0]*i10, O1[nbk][1]*i10);
            *(float2*)(ob24 + nbk*8 + 2*j) = make_float2(O1[nbk][2]*i11, O1[nbk][3]*i11);
        }
    }
}

// ---------------- launch ----------------
extern "C" void kernel_launch(void* const* d_in, const int* in_sizes, int n_in,
                              void* d_out, int out_size)
{
    const float* q  = (const float*)d_in[0];
    const float* k  = (const float*)d_in[1];
    const float* v  = (const float*)d_in[2];
    const float* Wc = (const float*)d_in[3];
    const float* bc = (const float*)d_in[4];
    const float* cb = (const float*)d_in[5];

    int B    = in_sizes[6];
    int C    = in_sizes[3] / CS;
    int Lk   = in_sizes[1] / (B * C);
    int Lq   = in_sizes[0] / (B * C);
    int nTok = B * Lk;
    (void)n_in; (void)out_size;

    zero_counts_kernel<<<(B * KC + 255) / 256, 256>>>(B * KC);
    idx_kernel<<<(nTok + 63) / 64, 256>>>(k, Wc, bc, Lk, nTok);
    scan_kernel<<<B, 256>>>(Lk);
    scatter_kernel<<<(nTok + 255) / 256, 256>>>(Lk, nTok);
    gather_kernel<<<B * KC, 256>>>(v);

    cudaFuncSetAttribute(attn_kernel,
                         cudaFuncAttributeMaxDynamicSharedMemorySize, SM_TOT);
    dim3 grid(NH, B);
    attn_kernel<<<grid, 256, SM_TOT>>>(q, cb, (float*)d_out, Lq);
}

// round 9
// speedup vs baseline: 4.1888x; 1.0260x over previous
#include <cuda_runtime.h>
#include <cuda_fp16.h>
#include <math.h>
#include <stdint.h>

#define CS    8
#define KC    256
#define NH    16
#define D     64
#define CDIM  1024
#define MAXB  8
#define MAXLK 4096
#define MAXTOK (MAXB*MAXLK)

// ---------------- device scratch ----------------
__device__ int   g_idx[MAXTOK];
__device__ int   g_counts[MAXB*KC];
__device__ int   g_offsets[MAXB*KC];
__device__ int   g_cursor[MAXB*KC];
__device__ int   g_perm[MAXTOK];
__device__ float g_codv[MAXB*KC*CDIM];          // [b][bucket][C]  8 MB

// ---------------- helpers ----------------
__device__ __forceinline__ uint32_t pack_h2(float a, float b) {
    __half2 h = __floats2half2_rn(a, b);
    return *(uint32_t*)&h;
}
__device__ __forceinline__ uint32_t hadd2_u(uint32_t a, uint32_t b) {
    __half2 r = __hadd2(*(__half2*)&a, *(__half2*)&b);
    return *(uint32_t*)&r;
}
__device__ __forceinline__ uint32_t ex2_h2(uint32_t x) {
    uint32_t r; asm("ex2.approx.f16x2 %0, %1;" : "=r"(r) : "r"(x)); return r;
}
__device__ __forceinline__ void mma_f16(float c[4], const uint32_t a[4],
                                        uint32_t b0, uint32_t b1) {
    asm volatile("mma.sync.aligned.m16n8k16.row.col.f32.f16.f16.f32 "
        "{%0,%1,%2,%3}, {%4,%5,%6,%7}, {%8,%9}, {%0,%1,%2,%3};"
        : "+f"(c[0]), "+f"(c[1]), "+f"(c[2]), "+f"(c[3])
        : "r"(a[0]), "r"(a[1]), "r"(a[2]), "r"(a[3]), "r"(b0), "r"(b1));
}

// ---------------- K0: zero counts ----------------
__global__ void zero_counts_kernel(int n) {
    int i = blockIdx.x * blockDim.x + threadIdx.x;
    if (i < n) g_counts[i] = 0;
}

// ---------------- K1: bucket index + histogram (W hoisted, 8 rows/iter) ----------------
__global__ void __launch_bounds__(256) idx_kernel(
    const float* __restrict__ k, const float* __restrict__ Wc,
    const float* __restrict__ bc, int Lk, int nTok)
{
    __shared__ float4 sW[CS * (CDIM/4)];   // 32 KB
    __shared__ float  sbc[CS];
    int t = threadIdx.x;
    for (int i = t; i < CS * (CDIM/4); i += 256) sW[i] = ((const float4*)Wc)[i];
    if (t < CS) sbc[t] = bc[t];
    __syncthreads();

    int warp = t >> 5, lane = t & 31;
    int rowBase = (blockIdx.x * 8 + warp) * 8;
    if (rowBase >= nTok) return;
    const float4* kbase = (const float4*)(k + (size_t)rowBase * CDIM);

    float acc[8][8];
    #pragma unroll
    for (int r = 0; r < 8; r++)
        #pragma unroll
        for (int j = 0; j < CS; j++) acc[r][j] = 0.f;

    for (int i = lane; i < CDIM/4; i += 32) {
        float4 wv[8];
        #pragma unroll
        for (int j = 0; j < CS; j++) wv[j] = sW[j * (CDIM/4) + i];
        #pragma unroll
        for (int r = 0; r < 8; r++) {
            float4 kv = kbase[(size_t)r * (CDIM/4) + i];
            #pragma unroll
            for (int j = 0; j < CS; j++)
                acc[r][j] += kv.x*wv[j].x + kv.y*wv[j].y + kv.z*wv[j].z + kv.w*wv[j].w;
        }
    }
    #pragma unroll
    for (int r = 0; r < 8; r++) {
        #pragma unroll
        for (int j = 0; j < CS; j++) {
            #pragma unroll
            for (int o = 16; o >= 1; o >>= 1)
                acc[r][j] += __shfl_xor_sync(0xffffffffu, acc[r][j], o);
        }
        if (lane == 0) {
            int rr = rowBase + r;
            int code = 0;
            #pragma unroll
            for (int j = 0; j < CS; j++)
                if (acc[r][j] + sbc[j] >= 0.f) code |= (1 << (7 - j));
            g_idx[rr] = code;
            int b = rr / Lk;
            atomicAdd(&g_counts[b * KC + code], 1);
        }
    }
}

// ---------------- K2: per-batch scan (one block per batch) ----------------
__global__ void scan_kernel(int Lk) {
    __shared__ int s[KC];
    int t = threadIdx.x, b = blockIdx.x;
    int v = g_counts[b * KC + t];
    s[t] = v;
    __syncthreads();
    for (int o = 1; o < KC; o <<= 1) {
        int x = (t >= o) ? s[t - o] : 0;
        __syncthreads();
        s[t] += x;
        __syncthreads();
    }
    int off = b * Lk + (s[t] - v);
    g_offsets[b * KC + t] = off;
    g_cursor[b * KC + t]  = off;
}

// ---------------- K3: scatter ----------------
__global__ void scatter_kernel(int Lk, int nTok) {
    int r = blockIdx.x * blockDim.x + threadIdx.x;
    if (r >= nTok) return;
    int b = r / Lk;
    int code = g_idx[r];
    int pos = atomicAdd(&g_cursor[b * KC + code], 1);
    g_perm[pos] = r;
}

// ---------------- K5: gather-sum v per bucket (4-way MLP, fixed tree) ----------------
__global__ void __launch_bounds__(256) gather_kernel(const float* __restrict__ v) {
    int bk = blockIdx.x;
    int t0 = g_offsets[bk];
    int cnt = g_counts[bk];
    __shared__ int toks[1024];
    int t = threadIdx.x;
    int n = min(cnt, 1024);
    for (int i = t; i < n; i += 256) toks[i] = g_perm[t0 + i];
    __syncthreads();
    if (t == 0 && n > 1) {
        for (int i = 1; i < n; i++) {
            int key = toks[i]; int j = i - 1;
            while (j >= 0 && toks[j] > key) { toks[j + 1] = toks[j]; j--; }
            toks[j + 1] = key;
        }
    }
    __syncthreads();

    float4 a0 = make_float4(0.f,0.f,0.f,0.f), a1 = a0, a2 = a0, a3 = a0;
    int i = 0;
    for (; i + 4 <= cnt; i += 4) {
        int r0 = (i     < n) ? toks[i]     : g_perm[t0 + i];
        int r1 = (i + 1 < n) ? toks[i + 1] : g_perm[t0 + i + 1];
        int r2 = (i + 2 < n) ? toks[i + 2] : g_perm[t0 + i + 2];
        int r3 = (i + 3 < n) ? toks[i + 3] : g_perm[t0 + i + 3];
        float4 x0 = *(const float4*)(v + (size_t)r0 * CDIM + t * 4);
        float4 x1 = *(const float4*)(v + (size_t)r1 * CDIM + t * 4);
        float4 x2 = *(const float4*)(v + (size_t)r2 * CDIM + t * 4);
        float4 x3 = *(const float4*)(v + (size_t)r3 * CDIM + t * 4);
        a0.x += x0.x; a0.y += x0.y; a0.z += x0.z; a0.w += x0.w;
        a1.x += x1.x; a1.y += x1.y; a1.z += x1.z; a1.w += x1.w;
        a2.x += x2.x; a2.y += x2.y; a2.z += x2.z; a2.w += x2.w;
        a3.x += x3.x; a3.y += x3.y; a3.z += x3.z; a3.w += x3.w;
    }
    for (; i < cnt; i++) {
        int r0 = (i < n) ? toks[i] : g_perm[t0 + i];
        float4 x0 = *(const float4*)(v + (size_t)r0 * CDIM + t * 4);
        a0.x += x0.x; a0.y += x0.y; a0.z += x0.z; a0.w += x0.w;
    }
    float4 acc;
    acc.x = (a0.x + a1.x) + (a2.x + a3.x);
    acc.y = (a0.y + a1.y) + (a2.y + a3.y);
    acc.z = (a0.z + a1.z) + (a2.z + a3.z);
    acc.w = (a0.w + a1.w) + (a2.w + a3.w);
    *(float4*)(g_codv + (size_t)bk * CDIM + t * 4) = acc;
}

// ---------------- K6: low-rank fp16 bucketed attention, M=32/warp ----------------
// S = (Q·cbT)·baseT : T[rows,16] via cb frags, then S via 0/1 base frags.
// grid(NH, B), 256 threads = 8 warps, 1 CTA/SM (~121KB smem).
// Scores in log2 domain (log2e*scale folded into cb); additive -inf mask;
// den via counts column (dim col 64 of V). Chunk loop unrolled 2x so the
// scheduler overlaps chunk i's ex2->PV chain with chunk i+1's S-MMAs.
#define CB_OFF  0
#define BA_OFF  3072
#define V_OFF   11264
#define CNT_OFF 54272
#define MSK_OFF 55296
#define VST_OFF 55808
#define SM_TOT  (VST_OFF + KC*D*4)     // 121344

__global__ void __launch_bounds__(256, 1) attn_kernel(
    const float* __restrict__ q, const float* __restrict__ cb,
    float* __restrict__ out, int Lq)
{
    extern __shared__ char sm[];
    uint32_t* Cbs  = (uint32_t*)(sm + CB_OFF);
    uint2*    BA2  = (uint2*)   (sm + BA_OFF);
    uint32_t* Vsm  = (uint32_t*)(sm + V_OFF);
    float*    cntS = (float*)   (sm + CNT_OFF);
    uint32_t* mskS = (uint32_t*)(sm + MSK_OFF);
    float*    Vst  = (float*)   (sm + VST_OFF);

    const int t = threadIdx.x, lane = t & 31, w = t >> 5;
    const int h = blockIdx.x, b = blockIdx.y;
    const int j = lane & 3, g = lane >> 2;
    const float QS = 0.125f * 1.4426950408889634f;   // scale * log2(e)

    // ---- Phase A: pack cb frags (QS folded), base frags, zero V slot-4,
    //      stage cod_v slice, counts ----
    #pragma unroll
    for (int i = 0; i < 2; i++) {
        int s = t + 256 * i;              // 512 float2 : n = j-coef row, p = dim pair
        int n = s >> 5, p = s & 31;
        const float* src = cb + (size_t)n * CDIM + h * D + 2 * (p);
        float2 x = make_float2(src[0] * QS, src[1] * QS);
        int jj = p & 3, qq = p >> 2;
        int kc = qq >> 1, ww = qq & 1;
        int slot = kc >> 1, c = ((kc & 1) << 1) | ww;
        Cbs[((n*4 + jj)*3 + slot)*4 + c] = pack_h2(x.x, x.y);
    }
    #pragma unroll
    for (int i = 0; i < 4; i++) {
        int s = t + 256 * i;              // 1024 : bucket n, jj
        int n = s >> 2, jj = s & 3;
        float b0a = (float)((n >> (7 - 2*jj)) & 1);
        float b0b = (float)((n >> (7 - (2*jj+1))) & 1);
        BA2[n*4 + jj] = make_uint2(pack_h2(b0a, b0b),
                                   pack_h2(1.f - b0a, 1.f - b0b));
    }
    for (int i = t; i < 64*8; i += 256) {
        int row = i >> 3, gg = i & 7;
        uint32_t* p4 = &Vsm[(row*42 + gg*5 + 4)*4];
        p4[0] = 0; p4[1] = 0; p4[2] = 0; p4[3] = 0;
    }
    {   // stage cod_v (b,h) slice: [256 buckets][64 dims]
        const float4* vsrc = (const float4*)(g_codv + ((size_t)b * KC) * CDIM + h * D);
        float4* vst4 = (float4*)Vst;
        #pragma unroll
        for (int i = 0; i < 16; i++) {
            int s = t + 256 * i;
            int n = s >> 4, c4 = s & 15;
            vst4[n * 16 + c4] = vsrc[(size_t)n * (CDIM/4) + c4];
        }
    }
    cntS[t] = (float)g_counts[b * KC + t];
    __syncthreads();

    // ---- Phase B: pack V^T frags from staging, counts column, masks ----
    #pragma unroll
    for (int i = 0; i < 32; i++) {
        int s = t + 256 * i;
        int d = s & 63, p = s >> 6;
        float x0 = Vst[(2*p)     * 64 + d];
        float x1 = Vst[(2*p + 1) * 64 + d];
        int ch = p >> 3, r = p & 7;
        int jj = r & 3, ww = r >> 2;
        int nbk = d >> 3, gg = d & 7;
        int slot = nbk >> 1, c = ((nbk & 1) << 1) | ww;
        Vsm[(((ch*4 + jj)*42) + gg*5 + slot)*4 + c] = pack_h2(x0, x1);
    }
    if (t < 64) {                          // counts column at dim col 64 (g=0)
        int ch = t >> 2, jj = t & 3;
        uint32_t* p4 = &Vsm[(t*42 + 4)*4];
        p4[0] = pack_h2(cntS[ch*16 + 2*jj],     cntS[ch*16 + 2*jj + 1]);
        p4[1] = pack_h2(cntS[ch*16 + 8 + 2*jj], cntS[ch*16 + 8 + 2*jj + 1]);
    }
    if (t < KC/2) {
        uint32_t m = 0;
        if (!(cntS[2*t]     > 0.f)) m |= 0xFC00u;
        if (!(cntS[2*t + 1] > 0.f)) m |= 0xFC00u << 16;
        mskS[t] = m;
    }
    __syncthreads();

    const uint4* CB4 = (const uint4*)Cbs;
    const uint4* VB  = (const uint4*)Vsm;

    // cb B-frags for T (rows g and 8+g), loaded once
    uint4 cbA0 = CB4[(g*4 + j)*3 + 0];
    uint4 cbA1 = CB4[(g*4 + j)*3 + 1];
    uint4 cbB0 = CB4[((8+g)*4 + j)*3 + 0];
    uint4 cbB1 = CB4[((8+g)*4 + j)*3 + 1];

    for (int q0 = 0; q0 < Lq; q0 += 256) {
        // ---- T = Q @ cb^T for two m16 blocks; convert C-frag -> A-frag ----
        uint32_t AT0[4], AT1[4];
        {
            const float* qr0 = q + (size_t)(b * Lq + q0 + w * 32 + g) * CDIM + h * D;
            const float* qr8 = qr0 + 8 * CDIM;
            uint32_t qa[4][4];
            #pragma unroll
            for (int kc = 0; kc < 4; kc++) {
                float2 x0 = *(const float2*)(qr0 + kc*16 + 2*j);
                float2 x1 = *(const float2*)(qr8 + kc*16 + 2*j);
                float2 x2 = *(const float2*)(qr0 + kc*16 + 8 + 2*j);
                float2 x3 = *(const float2*)(qr8 + kc*16 + 8 + 2*j);
                qa[kc][0] = pack_h2(x0.x, x0.y);
                qa[kc][1] = pack_h2(x1.x, x1.y);
                qa[kc][2] = pack_h2(x2.x, x2.y);
                qa[kc][3] = pack_h2(x3.x, x3.y);
            }
            float Tlo[4] = {0.f,0.f,0.f,0.f}, Thi[4] = {0.f,0.f,0.f,0.f};
            mma_f16(Tlo, qa[0], cbA0.x, cbA0.y);
            mma_f16(Tlo, qa[1], cbA0.z, cbA0.w);
            mma_f16(Tlo, qa[2], cbA1.x, cbA1.y);
            mma_f16(Tlo, qa[3], cbA1.z, cbA1.w);
            mma_f16(Thi, qa[0], cbB0.x, cbB0.y);
            mma_f16(Thi, qa[1], cbB0.z, cbB0.w);
            mma_f16(Thi, qa[2], cbB1.x, cbB1.y);
            mma_f16(Thi, qa[3], cbB1.z, cbB1.w);
            AT0[0] = pack_h2(Tlo[0], Tlo[1]);
            AT0[1] = pack_h2(Tlo[2], Tlo[3]);
            AT0[2] = pack_h2(Thi[0], Thi[1]);
            AT0[3] = pack_h2(Thi[2], Thi[3]);
        }
        {
            const float* qr16 = q + (size_t)(b * Lq + q0 + w * 32 + 16 + g) * CDIM + h * D;
            const float* qr24 = qr16 + 8 * CDIM;
            uint32_t qa[4][4];
            #pragma unroll
            for (int kc = 0; kc < 4; kc++) {
                float2 x0 = *(const float2*)(qr16 + kc*16 + 2*j);
                float2 x1 = *(const float2*)(qr24 + kc*16 + 2*j);
                float2 x2 = *(const float2*)(qr16 + kc*16 + 8 + 2*j);
                float2 x3 = *(const float2*)(qr24 + kc*16 + 8 + 2*j);
                qa[kc][0] = pack_h2(x0.x, x0.y);
                qa[kc][1] = pack_h2(x1.x, x1.y);
                qa[kc][2] = pack_h2(x2.x, x2.y);
                qa[kc][3] = pack_h2(x3.x, x3.y);
            }
            float Tlo[4] = {0.f,0.f,0.f,0.f}, Thi[4] = {0.f,0.f,0.f,0.f};
            mma_f16(Tlo, qa[0], cbA0.x, cbA0.y);
            mma_f16(Tlo, qa[1], cbA0.z, cbA0.w);
            mma_f16(Tlo, qa[2], cbA1.x, cbA1.y);
            mma_f16(Tlo, qa[3], cbA1.z, cbA1.w);
            mma_f16(Thi, qa[0], cbB0.x, cbB0.y);
            mma_f16(Thi, qa[1], cbB0.z, cbB0.w);
            mma_f16(Thi, qa[2], cbB1.x, cbB1.y);
            mma_f16(Thi, qa[3], cbB1.z, cbB1.w);
            AT1[0] = pack_h2(Tlo[0], Tlo[1]);
            AT1[1] = pack_h2(Tlo[2], Tlo[3]);
            AT1[2] = pack_h2(Thi[0], Thi[1]);
            AT1[3] = pack_h2(Thi[2], Thi[3]);
        }

        float O0[8][4], O1[8][4];
        #pragma unroll
        for (int nb = 0; nb < 8; nb++) {
            O0[nb][0]=0.f; O0[nb][1]=0.f; O0[nb][2]=0.f; O0[nb][3]=0.f;
            O1[nb][0]=0.f; O1[nb][1]=0.f; O1[nb][2]=0.f; O1[nb][3]=0.f;
        }
        float O8a[4] = {0.f,0.f,0.f,0.f}, O8b[4] = {0.f,0.f,0.f,0.f};

        #pragma unroll 2
        for (int ch = 0; ch < 16; ch++) {
            // ---- S(log2) = T @ base^T : buckets [ch*16, ch*16+16) ----
            uint2 ba = BA2[(ch*16 + g)*4 + j];
            uint2 bb = BA2[(ch*16 + 8 + g)*4 + j];
            float s0lo[4] = {0.f,0.f,0.f,0.f}, s0hi[4] = {0.f,0.f,0.f,0.f};
            float s1lo[4] = {0.f,0.f,0.f,0.f}, s1hi[4] = {0.f,0.f,0.f,0.f};
            mma_f16(s0lo, AT0, ba.x, ba.y);
            mma_f16(s0hi, AT0, bb.x, bb.y);
            mma_f16(s1lo, AT1, ba.x, ba.y);
            mma_f16(s1hi, AT1, bb.x, bb.y);

            uint32_t mlo = mskS[ch*8 + j], mhi = mskS[ch*8 + 4 + j];
            uint32_t A0[4], A1[4];
            A0[0] = ex2_h2(hadd2_u(pack_h2(s0lo[0], s0lo[1]), mlo));
            A0[1] = ex2_h2(hadd2_u(pack_h2(s0lo[2], s0lo[3]), mlo));
            A0[2] = ex2_h2(hadd2_u(pack_h2(s0hi[0], s0hi[1]), mhi));
            A0[3] = ex2_h2(hadd2_u(pack_h2(s0hi[2], s0hi[3]), mhi));
            A1[0] = ex2_h2(hadd2_u(pack_h2(s1lo[0], s1lo[1]), mlo));
            A1[1] = ex2_h2(hadd2_u(pack_h2(s1lo[2], s1lo[3]), mlo));
            A1[2] = ex2_h2(hadd2_u(pack_h2(s1hi[0], s1hi[1]), mhi));
            A1[3] = ex2_h2(hadd2_u(pack_h2(s1hi[2], s1hi[3]), mhi));

            const uint4* vrow = VB + (ch*4 + j)*42 + g*5;
            #pragma unroll
            for (int s = 0; s < 4; s++) {
                uint4 vv = vrow[s];
                mma_f16(O0[2*s],     A0, vv.x, vv.y);
                mma_f16(O0[2*s + 1], A0, vv.z, vv.w);
                mma_f16(O1[2*s],     A1, vv.x, vv.y);
                mma_f16(O1[2*s + 1], A1, vv.z, vv.w);
            }
            uint4 vc = vrow[4];
            mma_f16(O8a, A0, vc.x, vc.y);
            mma_f16(O8b, A1, vc.x, vc.y);
        }

        // ---- den at col 64 (j=0 lanes), broadcast within quad ----
        int src = lane & 28;
        float d00 = __shfl_sync(0xffffffffu, O8a[0], src);
        float d01 = __shfl_sync(0xffffffffu, O8a[2], src);
        float d10 = __shfl_sync(0xffffffffu, O8b[0], src);
        float d11 = __shfl_sync(0xffffffffu, O8b[2], src);
        float i00 = 1.0f / d00, i01 = 1.0f / d01;
        float i10 = 1.0f / d10, i11 = 1.0f / d11;

        // ---- epilogue: two blocks ----
        float* ob0  = out + (size_t)(b * Lq + q0 + w * 32 + g) * CDIM + h * D;
        float* ob8  = ob0 + 8  * CDIM;
        float* ob16 = ob0 + 16 * CDIM;
        float* ob24 = ob0 + 24 * CDIM;
        #pragma unroll
        for (int nbk = 0; nbk < 8; nbk++) {
            *(float2*)(ob0  + nbk*8 + 2*j) = make_float2(O0[nbk][0]*i00, O0[nbk][1]*i00);
            *(float2*)(ob8  + nbk*8 + 2*j) = make_float2(O0[nbk][2]*i01, O0[nbk][3]*i01);
            *(float2*)(ob16 + nbk*8 + 2*j) = make_float2(O1[nbk][0]*i10, O1[nbk][1]*i10);
            *(float2*)(ob24 + nbk*8 + 2*j) = make_float2(O1[nbk][2]*i11, O1[nbk][3]*i11);
        }
    }
}

// ---------------- launch ----------------
extern "C" void kernel_launch(void* const* d_in, const int* in_sizes, int n_in,
                              void* d_out, int out_size)
{
    const float* q  = (const float*)d_in[0];
    const float* k  = (const float*)d_in[1];
    const float* v  = (const float*)d_in[2];
    const float* Wc = (const float*)d_in[3];
    const float* bc = (const float*)d_in[4];
    const float* cb = (const float*)d_in[5];

    int B    = in_sizes[6];
    int C    = in_sizes[3] / CS;
    int Lk   = in_sizes[1] / (B * C);
    int Lq   = in_sizes[0] / (B * C);
    int nTok = B * Lk;
    (void)n_in; (void)out_size;

    zero_counts_kernel<<<(B * KC + 255) / 256, 256>>>(B * KC);
    idx_kernel<<<(nTok + 63) / 64, 256>>>(k, Wc, bc, Lk, nTok);
    scan_kernel<<<B, 256>>>(Lk);
    scatter_kernel<<<(nTok + 255) / 256, 256>>>(Lk, nTok);
    gather_kernel<<<B * KC, 256>>>(v);

    cudaFuncSetAttribute(attn_kernel,
                         cudaFuncAttributeMaxDynamicSharedMemorySize, SM_TOT);
    dim3 grid(NH, B);
    attn_kernel<<<grid, 256, SM_TOT>>>(q, cb, (float*)d_out, Lq);
}